// round 1
// baseline (speedup 1.0000x reference)
#include <cuda_runtime.h>

#define NB 2
#define SEQ 2048
#define EMB 1024
#define NHEADS 16
#define HD 64

// Scratch (allocation-free rule: __device__ globals)
__device__ float g_qp[NB * SEQ * EMB];
__device__ float g_kp[NB * SEQ * EMB];
__device__ float g_vp[NB * SEQ * EMB];
__device__ float g_ao[NB * SEQ * EMB];

// ---------------------------------------------------------------------------
// Kernel 1: per-head projections. X viewed as (N*S*H, 64) rows, out = X @ W^T.
// grid.x = 65536/64 row-tiles, grid.y = {q,k,v}
// ---------------------------------------------------------------------------
__global__ __launch_bounds__(256) void proj_kernel(
    const float* __restrict__ Xq, const float* __restrict__ Xk, const float* __restrict__ Xv,
    const float* __restrict__ Wq, const float* __restrict__ Wk, const float* __restrict__ Wv)
{
    const float* X;
    const float* W;
    float* O;
    if (blockIdx.y == 0)      { X = Xq; W = Wq; O = g_qp; }
    else if (blockIdx.y == 1) { X = Xk; W = Wk; O = g_kp; }
    else                      { X = Xv; W = Wv; O = g_vp; }

    __shared__ float Xs[64][65];   // padded: conflict-free row-strided reads
    __shared__ float Wt[64][64];   // Wt[d][e] = W[e][d]

    const int tid = threadIdx.x;

    // load W transposed
    for (int i = tid; i < 64 * 64; i += 256) {
        int e = i >> 6, d = i & 63;
        Wt[d][e] = W[i];
    }
    // load 64 input rows (float4-coalesced)
    const long rowbase = (long)blockIdx.x * 64;
    for (int i = tid; i < 64 * 16; i += 256) {
        int r = i >> 4, c4 = (i & 15) * 4;
        float4 v = *(const float4*)(X + (rowbase + r) * 64 + c4);
        Xs[r][c4 + 0] = v.x; Xs[r][c4 + 1] = v.y; Xs[r][c4 + 2] = v.z; Xs[r][c4 + 3] = v.w;
    }
    __syncthreads();

    const int row = tid >> 2;          // 0..63
    const int e0  = (tid & 3) * 16;    // 16 outputs per thread

    float acc[16];
#pragma unroll
    for (int j = 0; j < 16; j++) acc[j] = 0.f;

#pragma unroll
    for (int d = 0; d < 64; d++) {
        float x = Xs[row][d];
#pragma unroll
        for (int j4 = 0; j4 < 4; j4++) {
            float4 w = *(const float4*)(&Wt[d][e0 + j4 * 4]);
            acc[j4 * 4 + 0] += x * w.x;
            acc[j4 * 4 + 1] += x * w.y;
            acc[j4 * 4 + 2] += x * w.z;
            acc[j4 * 4 + 3] += x * w.w;
        }
    }

    float* outp = O + (rowbase + row) * 64 + e0;
#pragma unroll
    for (int j4 = 0; j4 < 4; j4++) {
        *(float4*)(outp + j4 * 4) =
            make_float4(acc[j4 * 4 + 0], acc[j4 * 4 + 1], acc[j4 * 4 + 2], acc[j4 * 4 + 3]);
    }
}

// ---------------------------------------------------------------------------
// Kernel 2: flash-style attention, 1 thread per query row, 128 rows / block.
// Reference semantics: energy = where(mask==0, 1e20, q.k); softmax(energy/32).
// Equivalent: s = mask ? (q.k)/32 : 3.125e18; online softmax over k.
// ---------------------------------------------------------------------------
__global__ __launch_bounds__(128) void attn_kernel(const int* __restrict__ mask)
{
    const int n = blockIdx.z;
    const int h = blockIdx.y;
    const int tid = threadIdx.x;
    const int qrow = blockIdx.x * 128 + tid;

    __shared__ float Ks[64][64];
    __shared__ float Vs[64][64];

    // load this thread's query row into registers
    float q[64];
    {
        const float* qptr = g_qp + (((long)n * SEQ + qrow) * NHEADS + h) * HD;
#pragma unroll
        for (int j = 0; j < 16; j++) {
            float4 v = *(const float4*)(qptr + j * 4);
            q[4 * j + 0] = v.x; q[4 * j + 1] = v.y; q[4 * j + 2] = v.z; q[4 * j + 3] = v.w;
        }
    }

    float o[64];
#pragma unroll
    for (int j = 0; j < 64; j++) o[j] = 0.f;
    float m = -3.4e38f, l = 0.f;

    const int* mrow = mask + ((long)n * SEQ + qrow) * SEQ;
    const float SCALE = 1.0f / 32.0f;
    const float MASKED = 3.125e18f;   // 1e20 / 32

    for (int k0 = 0; k0 < SEQ; k0 += 64) {
        __syncthreads();
        // cooperative K/V tile load (coalesced float4)
#pragma unroll
        for (int j = 0; j < 8; j++) {
            int idx = tid + j * 128;
            int r = idx >> 4, c = (idx & 15) * 4;
            long gaddr = (((long)n * SEQ + k0 + r) * NHEADS + h) * HD + c;
            *(float4*)(&Ks[r][c]) = *(const float4*)(g_kp + gaddr);
            *(float4*)(&Vs[r][c]) = *(const float4*)(g_vp + gaddr);
        }
        __syncthreads();

#pragma unroll 1
        for (int g = 0; g < 16; g++) {
            int4 mv = *(const int4*)(mrow + k0 + g * 4);
#pragma unroll
            for (int u = 0; u < 4; u++) {
                const int kk = g * 4 + u;
                const int mk = (u == 0) ? mv.x : (u == 1) ? mv.y : (u == 2) ? mv.z : mv.w;

                float s = 0.f;
#pragma unroll
                for (int j = 0; j < 16; j++) {
                    float4 kv = *(const float4*)(&Ks[kk][j * 4]);
                    s += q[4 * j + 0] * kv.x + q[4 * j + 1] * kv.y
                       + q[4 * j + 2] * kv.z + q[4 * j + 3] * kv.w;
                }
                s *= SCALE;
                if (mk == 0) s = MASKED;

                if (s > m) {
                    float corr = __expf(fmaxf(m - s, -87.f));
                    l *= corr;
#pragma unroll
                    for (int j = 0; j < 64; j++) o[j] *= corr;
                    m = s;
                }
                float p = __expf(fmaxf(s - m, -87.f));
                l += p;
#pragma unroll
                for (int j = 0; j < 16; j++) {
                    float4 vv = *(const float4*)(&Vs[kk][j * 4]);
                    o[4 * j + 0] += p * vv.x;
                    o[4 * j + 1] += p * vv.y;
                    o[4 * j + 2] += p * vv.z;
                    o[4 * j + 3] += p * vv.w;
                }
            }
        }
    }

    const float inv = 1.f / l;
    float* op = g_ao + ((long)n * SEQ + qrow) * EMB + h * HD;
#pragma unroll
    for (int j = 0; j < 16; j++) {
        *(float4*)(op + 4 * j) = make_float4(o[4 * j + 0] * inv, o[4 * j + 1] * inv,
                                             o[4 * j + 2] * inv, o[4 * j + 3] * inv);
    }
}

// ---------------------------------------------------------------------------
// Kernel 3: output projection Y = g_ao @ Wo^T + bo
// 64x64 tiles, BK=32, 256 threads, 4x4 register micro-tiles.
// ---------------------------------------------------------------------------
__global__ __launch_bounds__(256) void outproj_kernel(
    const float* __restrict__ Wo, const float* __restrict__ bo, float* __restrict__ Y)
{
    __shared__ float Xs[32][68];
    __shared__ float Ws[32][68];

    const int tid = threadIdx.x;
    const int r0 = blockIdx.y * 64;
    const int e0 = blockIdx.x * 64;
    const int tr = (tid >> 4) * 4;
    const int tc = (tid & 15) * 4;

    float acc[4][4];
#pragma unroll
    for (int i = 0; i < 4; i++)
#pragma unroll
        for (int j = 0; j < 4; j++) acc[i][j] = 0.f;

    for (int k0 = 0; k0 < EMB; k0 += 32) {
        __syncthreads();
#pragma unroll
        for (int it = 0; it < 2; it++) {
            int id = tid + it * 256;          // 0..511
            int r = id >> 3;                  // 0..63
            int c4 = (id & 7) * 4;            // 0..28
            float4 v = *(const float4*)(g_ao + (long)(r0 + r) * EMB + k0 + c4);
            Xs[c4 + 0][r] = v.x; Xs[c4 + 1][r] = v.y; Xs[c4 + 2][r] = v.z; Xs[c4 + 3][r] = v.w;
            float4 w = *(const float4*)(Wo + (long)(e0 + r) * EMB + k0 + c4);
            Ws[c4 + 0][r] = w.x; Ws[c4 + 1][r] = w.y; Ws[c4 + 2][r] = w.z; Ws[c4 + 3][r] = w.w;
        }
        __syncthreads();

#pragma unroll
        for (int k = 0; k < 32; k++) {
            float4 xv = *(const float4*)(&Xs[k][tr]);
            float4 wv = *(const float4*)(&Ws[k][tc]);
            float xr[4] = {xv.x, xv.y, xv.z, xv.w};
            float we[4] = {wv.x, wv.y, wv.z, wv.w};
#pragma unroll
            for (int i = 0; i < 4; i++)
#pragma unroll
                for (int j = 0; j < 4; j++) acc[i][j] += xr[i] * we[j];
        }
    }

    float4 bv = *(const float4*)(bo + e0 + tc);
    float bb[4] = {bv.x, bv.y, bv.z, bv.w};
#pragma unroll
    for (int i = 0; i < 4; i++) {
        *(float4*)(Y + (long)(r0 + tr + i) * EMB + e0 + tc) =
            make_float4(acc[i][0] + bb[0], acc[i][1] + bb[1],
                        acc[i][2] + bb[2], acc[i][3] + bb[3]);
    }
}

// ---------------------------------------------------------------------------
extern "C" void kernel_launch(void* const* d_in, const int* in_sizes, int n_in,
                              void* d_out, int out_size)
{
    const float* value = (const float*)d_in[0];
    const float* key   = (const float*)d_in[1];
    const float* query = (const float*)d_in[2];
    const int*   mask  = (const int*)d_in[3];
    const float* Wv    = (const float*)d_in[4];
    const float* Wk    = (const float*)d_in[5];
    const float* Wq    = (const float*)d_in[6];
    const float* Wo    = (const float*)d_in[7];
    const float* bo    = (const float*)d_in[8];
    float* out = (float*)d_out;

    // 1) Q/K/V per-head projections: 65536 rows of 64, 64 rows per block
    {
        dim3 grid(NB * SEQ * NHEADS / 64, 3);
        proj_kernel<<<grid, 256>>>(query, key, value, Wq, Wk, Wv);
    }
    // 2) attention
    {
        dim3 grid(SEQ / 128, NHEADS, NB);
        attn_kernel<<<grid, 128>>>(mask);
    }
    // 3) output projection + bias
    {
        dim3 grid(EMB / 64, NB * SEQ / 64);
        outproj_kernel<<<grid, 256>>>(Wo, bo, out);
    }
}

// round 2
// speedup vs baseline: 9.9738x; 9.9738x over previous
#include <cuda_runtime.h>
#include <cstdint>

#define NB 2
#define SEQ 2048
#define EMB 1024
#define NHEADS 16
#define HD 64

// Scratch (allocation-free rule: __device__ globals)
__device__ float g_vp[NB * SEQ * EMB];     // projected V  (n, s, e)
__device__ float g_ao[NB * SEQ * EMB];     // masked-average output (n, s, e)
__device__ float g_woT[EMB * EMB];         // Wo transposed: woT[k][n] = Wo[n][k]
__device__ float g_invcnt[NB * SEQ];       // 1 / (# zeros in mask row)

// ---------------------------------------------------------------------------
// tf32 helpers
// ---------------------------------------------------------------------------
__device__ __forceinline__ float to_tf32(float x) {
    uint32_t u;
    asm("cvt.rna.tf32.f32 %0, %1;" : "=r"(u) : "f"(x));
    return __uint_as_float(u);
}

__device__ __forceinline__ void mma_tf32(float c[4],
                                         uint32_t a0, uint32_t a1, uint32_t a2, uint32_t a3,
                                         uint32_t b0, uint32_t b1) {
    asm volatile(
        "mma.sync.aligned.m16n8k8.row.col.f32.tf32.tf32.f32 "
        "{%0,%1,%2,%3}, {%4,%5,%6,%7}, {%8,%9}, {%0,%1,%2,%3};"
        : "+f"(c[0]), "+f"(c[1]), "+f"(c[2]), "+f"(c[3])
        : "r"(a0), "r"(a1), "r"(a2), "r"(a3), "r"(b0), "r"(b1));
}

// ---------------------------------------------------------------------------
// Kernel 1: V per-head projection. X viewed as (N*S*H, 64) rows, out = X @ Wv^T.
// ---------------------------------------------------------------------------
__global__ __launch_bounds__(256) void proj_v_kernel(
    const float* __restrict__ X, const float* __restrict__ W)
{
    __shared__ float Xs[64][65];
    __shared__ float Wt[64][64];   // Wt[d][e] = W[e][d]

    const int tid = threadIdx.x;

    for (int i = tid; i < 64 * 64; i += 256) {
        int e = i >> 6, d = i & 63;
        Wt[d][e] = W[i];
    }
    const long rowbase = (long)blockIdx.x * 64;
    for (int i = tid; i < 64 * 16; i += 256) {
        int r = i >> 4, c4 = (i & 15) * 4;
        float4 v = *(const float4*)(X + (rowbase + r) * 64 + c4);
        Xs[r][c4 + 0] = v.x; Xs[r][c4 + 1] = v.y; Xs[r][c4 + 2] = v.z; Xs[r][c4 + 3] = v.w;
    }
    __syncthreads();

    const int row = tid >> 2;
    const int e0  = (tid & 3) * 16;

    float acc[16];
#pragma unroll
    for (int j = 0; j < 16; j++) acc[j] = 0.f;

#pragma unroll
    for (int d = 0; d < 64; d++) {
        float x = Xs[row][d];
#pragma unroll
        for (int j4 = 0; j4 < 4; j4++) {
            float4 w = *(const float4*)(&Wt[d][e0 + j4 * 4]);
            acc[j4 * 4 + 0] += x * w.x;
            acc[j4 * 4 + 1] += x * w.y;
            acc[j4 * 4 + 2] += x * w.z;
            acc[j4 * 4 + 3] += x * w.w;
        }
    }

    float* outp = g_vp + (rowbase + row) * 64 + e0;
#pragma unroll
    for (int j4 = 0; j4 < 4; j4++) {
        *(float4*)(outp + j4 * 4) =
            make_float4(acc[j4 * 4 + 0], acc[j4 * 4 + 1], acc[j4 * 4 + 2], acc[j4 * 4 + 3]);
    }
}

// ---------------------------------------------------------------------------
// Kernel 2: per-row zero counts -> 1/count.  grid = N*S blocks, 256 threads.
// ---------------------------------------------------------------------------
__global__ __launch_bounds__(256) void count_kernel(const int* __restrict__ mask)
{
    const int tid = threadIdx.x;
    const long base = (long)blockIdx.x * SEQ;
    const int4* mp = (const int4*)(mask + base);

    int c = 0;
    int4 a = mp[tid];
    c += (a.x == 0) + (a.y == 0) + (a.z == 0) + (a.w == 0);
    int4 b = mp[tid + 256];
    c += (b.x == 0) + (b.y == 0) + (b.z == 0) + (b.w == 0);

#pragma unroll
    for (int off = 16; off > 0; off >>= 1)
        c += __shfl_down_sync(0xffffffffu, c, off);

    __shared__ int ws[8];
    if ((tid & 31) == 0) ws[tid >> 5] = c;
    __syncthreads();
    if (tid == 0) {
        int t = 0;
#pragma unroll
        for (int i = 0; i < 8; i++) t += ws[i];
        g_invcnt[blockIdx.x] = 1.0f / (float)t;
    }
}

// ---------------------------------------------------------------------------
// Kernel 3: Wo transpose (woT[k][n] = Wo[n][k])
// ---------------------------------------------------------------------------
__global__ __launch_bounds__(256) void transpose_kernel(const float* __restrict__ Wo)
{
    __shared__ float t[32][33];
    const int tx = threadIdx.x, ty = threadIdx.y;
    const int x = blockIdx.x * 32 + tx;         // k
    const int y0 = blockIdx.y * 32;             // n
#pragma unroll
    for (int j = 0; j < 4; j++)
        t[ty + j * 8][tx] = Wo[(long)(y0 + ty + j * 8) * EMB + x];
    __syncthreads();
    const int x2 = blockIdx.y * 32 + tx;        // n
    const int y2 = blockIdx.x * 32;             // k
#pragma unroll
    for (int j = 0; j < 4; j++)
        g_woT[(long)(y2 + ty + j * 8) * EMB + x2] = t[tx][ty + j * 8];
}

// ---------------------------------------------------------------------------
// Kernel 4: masked-sum GEMM via tf32 mma.sync.
// ao[row, e] = invcnt[row] * sum_{k: mask[row,k]==0} Vp[n, k, e]
// Block: 128(M) x 128(N), 8 warps (2x4), BK=32.
// ---------------------------------------------------------------------------
__global__ __launch_bounds__(256) void masked_sum_kernel(const int* __restrict__ mask)
{
    __shared__ float As[128][36];   // As[m][k], 0/1 from mask
    __shared__ float Bs[32][132];   // Bs[k][n], tf32-rounded Vp

    const int tid = threadIdx.x;
    const int wid = tid >> 5, lane = tid & 31;
    const int gid = lane >> 2, tig = lane & 3;
    const int wm = (wid >> 2) * 64;
    const int wn = (wid & 3) * 32;

    const int e0 = blockIdx.x * 128;
    const int row0 = blockIdx.y * 128;         // [0, NB*SEQ)
    const int n = row0 / SEQ;
    const int q0 = row0 % SEQ;

    const int* mbase = mask + (long)n * SEQ * SEQ + (long)q0 * SEQ;
    const float* vbase = g_vp + (long)n * SEQ * EMB;

    float acc[4][4][4];
#pragma unroll
    for (int a = 0; a < 4; a++)
#pragma unroll
        for (int b = 0; b < 4; b++)
#pragma unroll
            for (int c = 0; c < 4; c++) acc[a][b][c] = 0.f;

    const int lm  = tid >> 3;            // 0..31 (A loader row base)
    const int lk4 = (tid & 7) * 4;       // A loader k
    const int bn4 = (tid & 31) * 4;      // B loader n
    const int bk  = tid >> 5;            // B loader k base (0..7)

    for (int k0 = 0; k0 < SEQ; k0 += 32) {
        // A tile: binary mask -> 1.0 where mask==0
#pragma unroll
        for (int it = 0; it < 4; it++) {
            int m = lm + it * 32;
            int4 mv = *(const int4*)(mbase + (long)m * SEQ + k0 + lk4);
            float4 f;
            f.x = (mv.x == 0) ? 1.f : 0.f;
            f.y = (mv.y == 0) ? 1.f : 0.f;
            f.z = (mv.z == 0) ? 1.f : 0.f;
            f.w = (mv.w == 0) ? 1.f : 0.f;
            *(float4*)&As[m][lk4] = f;
        }
        // B tile: Vp rows, tf32-rounded
#pragma unroll
        for (int it = 0; it < 4; it++) {
            int k = bk + it * 8;
            float4 v = *(const float4*)(vbase + (long)(k0 + k) * EMB + e0 + bn4);
            v.x = to_tf32(v.x); v.y = to_tf32(v.y);
            v.z = to_tf32(v.z); v.w = to_tf32(v.w);
            *(float4*)&Bs[k][bn4] = v;
        }
        __syncthreads();

#pragma unroll
        for (int ks = 0; ks < 4; ks++) {
            const int kk = ks * 8;
            uint32_t a[4][4], b[4][2];
#pragma unroll
            for (int mt = 0; mt < 4; mt++) {
                int m = wm + mt * 16;
                a[mt][0] = __float_as_uint(As[m + gid][kk + tig]);
                a[mt][1] = __float_as_uint(As[m + gid + 8][kk + tig]);
                a[mt][2] = __float_as_uint(As[m + gid][kk + tig + 4]);
                a[mt][3] = __float_as_uint(As[m + gid + 8][kk + tig + 4]);
            }
#pragma unroll
            for (int nt = 0; nt < 4; nt++) {
                int nn = wn + nt * 8;
                b[nt][0] = __float_as_uint(Bs[kk + tig][nn + gid]);
                b[nt][1] = __float_as_uint(Bs[kk + tig + 4][nn + gid]);
            }
#pragma unroll
            for (int mt = 0; mt < 4; mt++)
#pragma unroll
                for (int nt = 0; nt < 4; nt++)
                    mma_tf32(acc[mt][nt], a[mt][0], a[mt][1], a[mt][2], a[mt][3],
                             b[nt][0], b[nt][1]);
        }
        __syncthreads();
    }

    // epilogue: scale by 1/count, store
#pragma unroll
    for (int mt = 0; mt < 4; mt++) {
        int r0a = row0 + wm + mt * 16 + gid;
        float s0 = g_invcnt[r0a];
        float s1 = g_invcnt[r0a + 8];
#pragma unroll
        for (int nt = 0; nt < 4; nt++) {
            int col = e0 + wn + nt * 8 + 2 * tig;
            float2 v0 = make_float2(acc[mt][nt][0] * s0, acc[mt][nt][1] * s0);
            float2 v1 = make_float2(acc[mt][nt][2] * s1, acc[mt][nt][3] * s1);
            *(float2*)(g_ao + (long)r0a * EMB + col) = v0;
            *(float2*)(g_ao + (long)(r0a + 8) * EMB + col) = v1;
        }
    }
}

// ---------------------------------------------------------------------------
// Kernel 5: output projection GEMM via tf32 mma.sync: out = ao @ Wo^T + bo
// Same skeleton; A = ao (tf32-rounded), B = woT.
// ---------------------------------------------------------------------------
__global__ __launch_bounds__(256) void outproj_mma_kernel(
    const float* __restrict__ bo, float* __restrict__ Y)
{
    __shared__ float As[128][36];
    __shared__ float Bs[32][132];

    const int tid = threadIdx.x;
    const int wid = tid >> 5, lane = tid & 31;
    const int gid = lane >> 2, tig = lane & 3;
    const int wm = (wid >> 2) * 64;
    const int wn = (wid & 3) * 32;

    const int e0 = blockIdx.x * 128;
    const int row0 = blockIdx.y * 128;

    float acc[4][4][4];
#pragma unroll
    for (int a = 0; a < 4; a++)
#pragma unroll
        for (int b = 0; b < 4; b++)
#pragma unroll
            for (int c = 0; c < 4; c++) acc[a][b][c] = 0.f;

    const int lm  = tid >> 3;
    const int lk4 = (tid & 7) * 4;
    const int bn4 = (tid & 31) * 4;
    const int bk  = tid >> 5;

    for (int k0 = 0; k0 < EMB; k0 += 32) {
#pragma unroll
        for (int it = 0; it < 4; it++) {
            int m = lm + it * 32;
            float4 v = *(const float4*)(g_ao + (long)(row0 + m) * EMB + k0 + lk4);
            v.x = to_tf32(v.x); v.y = to_tf32(v.y);
            v.z = to_tf32(v.z); v.w = to_tf32(v.w);
            *(float4*)&As[m][lk4] = v;
        }
#pragma unroll
        for (int it = 0; it < 4; it++) {
            int k = bk + it * 8;
            float4 v = *(const float4*)(g_woT + (long)(k0 + k) * EMB + e0 + bn4);
            v.x = to_tf32(v.x); v.y = to_tf32(v.y);
            v.z = to_tf32(v.z); v.w = to_tf32(v.w);
            *(float4*)&Bs[k][bn4] = v;
        }
        __syncthreads();

#pragma unroll
        for (int ks = 0; ks < 4; ks++) {
            const int kk = ks * 8;
            uint32_t a[4][4], b[4][2];
#pragma unroll
            for (int mt = 0; mt < 4; mt++) {
                int m = wm + mt * 16;
                a[mt][0] = __float_as_uint(As[m + gid][kk + tig]);
                a[mt][1] = __float_as_uint(As[m + gid + 8][kk + tig]);
                a[mt][2] = __float_as_uint(As[m + gid][kk + tig + 4]);
                a[mt][3] = __float_as_uint(As[m + gid + 8][kk + tig + 4]);
            }
#pragma unroll
            for (int nt = 0; nt < 4; nt++) {
                int nn = wn + nt * 8;
                b[nt][0] = __float_as_uint(Bs[kk + tig][nn + gid]);
                b[nt][1] = __float_as_uint(Bs[kk + tig + 4][nn + gid]);
            }
#pragma unroll
            for (int mt = 0; mt < 4; mt++)
#pragma unroll
                for (int nt = 0; nt < 4; nt++)
                    mma_tf32(acc[mt][nt], a[mt][0], a[mt][1], a[mt][2], a[mt][3],
                             b[nt][0], b[nt][1]);
        }
        __syncthreads();
    }

#pragma unroll
    for (int mt = 0; mt < 4; mt++) {
        int r0a = row0 + wm + mt * 16 + gid;
#pragma unroll
        for (int nt = 0; nt < 4; nt++) {
            int col = e0 + wn + nt * 8 + 2 * tig;
            float b0v = bo[col], b1v = bo[col + 1];
            float2 v0 = make_float2(acc[mt][nt][0] + b0v, acc[mt][nt][1] + b1v);
            float2 v1 = make_float2(acc[mt][nt][2] + b0v, acc[mt][nt][3] + b1v);
            *(float2*)(Y + (long)r0a * EMB + col) = v0;
            *(float2*)(Y + (long)(r0a + 8) * EMB + col) = v1;
        }
    }
}

// ---------------------------------------------------------------------------
extern "C" void kernel_launch(void* const* d_in, const int* in_sizes, int n_in,
                              void* d_out, int out_size)
{
    const float* value = (const float*)d_in[0];
    // d_in[1] = key   (unused: softmax collapses to masked average)
    // d_in[2] = query (unused)
    const int*   mask  = (const int*)d_in[3];
    const float* Wv    = (const float*)d_in[4];
    // d_in[5] = Wk (unused), d_in[6] = Wq (unused)
    const float* Wo    = (const float*)d_in[7];
    const float* bo    = (const float*)d_in[8];
    float* out = (float*)d_out;

    // 1) V per-head projection
    proj_v_kernel<<<NB * SEQ * NHEADS / 64, 256>>>(value, Wv);
    // 2) per-row zero counts
    count_kernel<<<NB * SEQ, 256>>>(mask);
    // 3) Wo transpose
    {
        dim3 grid(EMB / 32, EMB / 32), block(32, 8);
        transpose_kernel<<<grid, block>>>(Wo);
    }
    // 4) masked-average GEMM (tensor cores, tf32)
    {
        dim3 grid(EMB / 128, NB * SEQ / 128);
        masked_sum_kernel<<<grid, 256>>>(mask);
    }
    // 5) output projection GEMM + bias (tensor cores, tf32)
    {
        dim3 grid(EMB / 128, NB * SEQ / 128);
        outproj_mma_kernel<<<grid, 256>>>(bo, out);
    }
}

// round 3
// speedup vs baseline: 10.5296x; 1.0557x over previous
#include <cuda_runtime.h>
#include <cstdint>

#define NB 2
#define SEQ 2048
#define EMB 1024
#define NHEADS 16

// Scratch (__device__ globals per allocation rules)
__device__ float g_wcomb[EMB * EMB];       // folded Wv/Wo: [k'][n], tf32-rounded
__device__ float g_vc[NB * SEQ * EMB];     // V @ Wcomb:   [n*SEQ+s][e], tf32-rounded
__device__ float g_invcnt[NB * SEQ];       // 1 / (# zeros in mask row)

// ---------------------------------------------------------------------------
__device__ __forceinline__ float to_tf32(float x) {
    uint32_t u;
    asm("cvt.rna.tf32.f32 %0, %1;" : "=r"(u) : "f"(x));
    return __uint_as_float(u);
}

__device__ __forceinline__ void mma_tf32(float c[4],
                                         uint32_t a0, uint32_t a1, uint32_t a2, uint32_t a3,
                                         uint32_t b0, uint32_t b1) {
    asm volatile(
        "mma.sync.aligned.m16n8k8.row.col.f32.tf32.tf32.f32 "
        "{%0,%1,%2,%3}, {%4,%5,%6,%7}, {%8,%9}, {%0,%1,%2,%3};"
        : "+f"(c[0]), "+f"(c[1]), "+f"(c[2]), "+f"(c[3])
        : "r"(a0), "r"(a1), "r"(a2), "r"(a3), "r"(b0), "r"(b1));
}

// ---------------------------------------------------------------------------
// Kernel 1: Wcomb[h*64+d'][n] = sum_d Wv[d][d'] * Wo[n][h*64+d]   (fp32, tiny)
// grid = (16 heads, 16 n-tiles of 64), block 256
// ---------------------------------------------------------------------------
__global__ __launch_bounds__(256) void wcomb_kernel(
    const float* __restrict__ Wv, const float* __restrict__ Wo)
{
    __shared__ float sWv[64][68];    // sWv[d][d']
    __shared__ float sWoT[64][68];   // sWoT[d][c] = Wo[n0+c][h*64+d]

    const int h = blockIdx.x;
    const int n0 = blockIdx.y * 64;
    const int tid = threadIdx.x;

    for (int i = tid; i < 4096; i += 256) {
        int d = i >> 6, r = i & 63;
        sWv[d][r] = Wv[i];
    }
    for (int i = tid; i < 4096; i += 256) {
        int c = i >> 6, d = i & 63;
        sWoT[d][c] = Wo[(long)(n0 + c) * EMB + h * 64 + d];
    }
    __syncthreads();

    const int tr = (tid >> 4) * 4, tc = (tid & 15) * 4;
    float acc[4][4];
#pragma unroll
    for (int i = 0; i < 4; i++)
#pragma unroll
        for (int j = 0; j < 4; j++) acc[i][j] = 0.f;

#pragma unroll
    for (int d = 0; d < 64; d++) {
        float4 av = *(const float4*)&sWv[d][tr];
        float4 bv = *(const float4*)&sWoT[d][tc];
        float a[4] = {av.x, av.y, av.z, av.w};
        float b[4] = {bv.x, bv.y, bv.z, bv.w};
#pragma unroll
        for (int i = 0; i < 4; i++)
#pragma unroll
            for (int j = 0; j < 4; j++) acc[i][j] += a[i] * b[j];
    }

#pragma unroll
    for (int i = 0; i < 4; i++) {
        float4 v = make_float4(to_tf32(acc[i][0]), to_tf32(acc[i][1]),
                               to_tf32(acc[i][2]), to_tf32(acc[i][3]));
        *(float4*)(g_wcomb + (long)(h * 64 + tr + i) * EMB + n0 + tc) = v;
    }
}

// ---------------------------------------------------------------------------
// Kernel 2: per-row zero counts -> 1/count
// ---------------------------------------------------------------------------
__global__ __launch_bounds__(256) void count_kernel(const int* __restrict__ mask)
{
    const int tid = threadIdx.x;
    const long base = (long)blockIdx.x * SEQ;
    const int4* mp = (const int4*)(mask + base);

    int c = 0;
    int4 a = mp[tid];
    c += (a.x == 0) + (a.y == 0) + (a.z == 0) + (a.w == 0);
    int4 b = mp[tid + 256];
    c += (b.x == 0) + (b.y == 0) + (b.z == 0) + (b.w == 0);

#pragma unroll
    for (int off = 16; off > 0; off >>= 1)
        c += __shfl_down_sync(0xffffffffu, c, off);

    __shared__ int ws[8];
    if ((tid & 31) == 0) ws[tid >> 5] = c;
    __syncthreads();
    if (tid == 0) {
        int t = 0;
#pragma unroll
        for (int i = 0; i < 8; i++) t += ws[i];
        g_invcnt[blockIdx.x] = 1.0f / (float)t;
    }
}

// ---------------------------------------------------------------------------
// GEMM tiles: block 256(M) x 128(N), BK=16, 8 warps (4x2), warp tile 64x64.
// Register-prefetch double buffering. grid = (EMB/128, 4096/256) = 8x16 = 128.
// ---------------------------------------------------------------------------
#define BM 256
#define BN 128
#define BK 16
#define APAD 20
#define BPAD 136

// Kernel 3: Vc = value @ Wcomb  (A tf32-rounded at smem store, Wcomb pre-rounded)
__global__ __launch_bounds__(256) void vc_gemm_kernel(const float* __restrict__ V)
{
    __shared__ float As[BM][APAD];
    __shared__ float Bs[BK][BPAD];

    const int tid = threadIdx.x;
    const int wid = tid >> 5, lane = tid & 31;
    const int gid = lane >> 2, tig = lane & 3;
    const int wm = (wid >> 1) * 64;
    const int wn = (wid & 1) * 64;

    const int e0 = blockIdx.x * BN;
    const int row0 = blockIdx.y * BM;

    float acc[4][8][4];
#pragma unroll
    for (int a = 0; a < 4; a++)
#pragma unroll
        for (int b = 0; b < 8; b++)
#pragma unroll
            for (int c = 0; c < 4; c++) acc[a][b][c] = 0.f;

    const int am = tid >> 2;          // + it*64
    const int ak = (tid & 3) * 4;
    const int bk = tid >> 4;          // 0..15
    const int bn = (tid & 15) * 8;

    const float* Abase = V + (long)row0 * EMB;

    float4 pa[4], pb0, pb1;
    // preload k0 = 0
#pragma unroll
    for (int it = 0; it < 4; it++)
        pa[it] = *(const float4*)(Abase + (long)(am + it * 64) * EMB + ak);
    pb0 = *(const float4*)(g_wcomb + (long)bk * EMB + e0 + bn);
    pb1 = *(const float4*)(g_wcomb + (long)bk * EMB + e0 + bn + 4);
#pragma unroll
    for (int it = 0; it < 4; it++) {
        float4 v = pa[it];
        As[am + it * 64][ak + 0] = to_tf32(v.x);
        As[am + it * 64][ak + 1] = to_tf32(v.y);
        As[am + it * 64][ak + 2] = to_tf32(v.z);
        As[am + it * 64][ak + 3] = to_tf32(v.w);
    }
    *(float4*)&Bs[bk][bn] = pb0;
    *(float4*)&Bs[bk][bn + 4] = pb1;
    __syncthreads();

    for (int k0 = 0; k0 < EMB; k0 += BK) {
        const bool more = (k0 + BK) < EMB;
        if (more) {
            const int kp = k0 + BK;
#pragma unroll
            for (int it = 0; it < 4; it++)
                pa[it] = *(const float4*)(Abase + (long)(am + it * 64) * EMB + kp + ak);
            pb0 = *(const float4*)(g_wcomb + (long)(kp + bk) * EMB + e0 + bn);
            pb1 = *(const float4*)(g_wcomb + (long)(kp + bk) * EMB + e0 + bn + 4);
        }

#pragma unroll
        for (int ks = 0; ks < 2; ks++) {
            const int kk = ks * 8;
            uint32_t a[4][4], b[8][2];
#pragma unroll
            for (int mt = 0; mt < 4; mt++) {
                int m = wm + mt * 16;
                a[mt][0] = __float_as_uint(As[m + gid][kk + tig]);
                a[mt][1] = __float_as_uint(As[m + gid + 8][kk + tig]);
                a[mt][2] = __float_as_uint(As[m + gid][kk + tig + 4]);
                a[mt][3] = __float_as_uint(As[m + gid + 8][kk + tig + 4]);
            }
#pragma unroll
            for (int nt = 0; nt < 8; nt++) {
                int nn = wn + nt * 8;
                b[nt][0] = __float_as_uint(Bs[kk + tig][nn + gid]);
                b[nt][1] = __float_as_uint(Bs[kk + tig + 4][nn + gid]);
            }
#pragma unroll
            for (int mt = 0; mt < 4; mt++)
#pragma unroll
                for (int nt = 0; nt < 8; nt++)
                    mma_tf32(acc[mt][nt], a[mt][0], a[mt][1], a[mt][2], a[mt][3],
                             b[nt][0], b[nt][1]);
        }
        __syncthreads();
        if (more) {
#pragma unroll
            for (int it = 0; it < 4; it++) {
                float4 v = pa[it];
                As[am + it * 64][ak + 0] = to_tf32(v.x);
                As[am + it * 64][ak + 1] = to_tf32(v.y);
                As[am + it * 64][ak + 2] = to_tf32(v.z);
                As[am + it * 64][ak + 3] = to_tf32(v.w);
            }
            *(float4*)&Bs[bk][bn] = pb0;
            *(float4*)&Bs[bk][bn + 4] = pb1;
        }
        __syncthreads();
    }

    // epilogue: tf32-round and store Vc (consumed only by the masked GEMM)
#pragma unroll
    for (int mt = 0; mt < 4; mt++) {
        int r0a = row0 + wm + mt * 16 + gid;
#pragma unroll
        for (int nt = 0; nt < 8; nt++) {
            int col = e0 + wn + nt * 8 + 2 * tig;
            float2 v0 = make_float2(to_tf32(acc[mt][nt][0]), to_tf32(acc[mt][nt][1]));
            float2 v1 = make_float2(to_tf32(acc[mt][nt][2]), to_tf32(acc[mt][nt][3]));
            *(float2*)(g_vc + (long)r0a * EMB + col) = v0;
            *(float2*)(g_vc + (long)(r0a + 8) * EMB + col) = v1;
        }
    }
}

// Kernel 4: out = diag(invcnt) * (M0 @ Vc) + bo   (M0 = (mask==0), binary)
__global__ __launch_bounds__(256) void masked_gemm_kernel(
    const int* __restrict__ mask, const float* __restrict__ bo, float* __restrict__ Y)
{
    __shared__ float As[BM][APAD];
    __shared__ float Bs[BK][BPAD];

    const int tid = threadIdx.x;
    const int wid = tid >> 5, lane = tid & 31;
    const int gid = lane >> 2, tig = lane & 3;
    const int wm = (wid >> 1) * 64;
    const int wn = (wid & 1) * 64;

    const int e0 = blockIdx.x * BN;
    const int row0 = blockIdx.y * BM;
    const int n = row0 / SEQ;
    const int q0 = row0 % SEQ;

    const int* mbase = mask + (long)n * SEQ * SEQ + (long)q0 * SEQ;
    const float* vbase = g_vc + (long)n * SEQ * EMB;

    float acc[4][8][4];
#pragma unroll
    for (int a = 0; a < 4; a++)
#pragma unroll
        for (int b = 0; b < 8; b++)
#pragma unroll
            for (int c = 0; c < 4; c++) acc[a][b][c] = 0.f;

    const int am = tid >> 2;
    const int ak = (tid & 3) * 4;
    const int bk = tid >> 4;
    const int bn = (tid & 15) * 8;

    int4 pa[4];
    float4 pb0, pb1;
#pragma unroll
    for (int it = 0; it < 4; it++)
        pa[it] = *(const int4*)(mbase + (long)(am + it * 64) * SEQ + ak);
    pb0 = *(const float4*)(vbase + (long)bk * EMB + e0 + bn);
    pb1 = *(const float4*)(vbase + (long)bk * EMB + e0 + bn + 4);
#pragma unroll
    for (int it = 0; it < 4; it++) {
        int4 v = pa[it];
        As[am + it * 64][ak + 0] = (v.x == 0) ? 1.f : 0.f;
        As[am + it * 64][ak + 1] = (v.y == 0) ? 1.f : 0.f;
        As[am + it * 64][ak + 2] = (v.z == 0) ? 1.f : 0.f;
        As[am + it * 64][ak + 3] = (v.w == 0) ? 1.f : 0.f;
    }
    *(float4*)&Bs[bk][bn] = pb0;
    *(float4*)&Bs[bk][bn + 4] = pb1;
    __syncthreads();

    for (int k0 = 0; k0 < SEQ; k0 += BK) {
        const bool more = (k0 + BK) < SEQ;
        if (more) {
            const int kp = k0 + BK;
#pragma unroll
            for (int it = 0; it < 4; it++)
                pa[it] = *(const int4*)(mbase + (long)(am + it * 64) * SEQ + kp + ak);
            pb0 = *(const float4*)(vbase + (long)(kp + bk) * EMB + e0 + bn);
            pb1 = *(const float4*)(vbase + (long)(kp + bk) * EMB + e0 + bn + 4);
        }

#pragma unroll
        for (int ks = 0; ks < 2; ks++) {
            const int kk = ks * 8;
            uint32_t a[4][4], b[8][2];
#pragma unroll
            for (int mt = 0; mt < 4; mt++) {
                int m = wm + mt * 16;
                a[mt][0] = __float_as_uint(As[m + gid][kk + tig]);
                a[mt][1] = __float_as_uint(As[m + gid + 8][kk + tig]);
                a[mt][2] = __float_as_uint(As[m + gid][kk + tig + 4]);
                a[mt][3] = __float_as_uint(As[m + gid + 8][kk + tig + 4]);
            }
#pragma unroll
            for (int nt = 0; nt < 8; nt++) {
                int nn = wn + nt * 8;
                b[nt][0] = __float_as_uint(Bs[kk + tig][nn + gid]);
                b[nt][1] = __float_as_uint(Bs[kk + tig + 4][nn + gid]);
            }
#pragma unroll
            for (int mt = 0; mt < 4; mt++)
#pragma unroll
                for (int nt = 0; nt < 8; nt++)
                    mma_tf32(acc[mt][nt], a[mt][0], a[mt][1], a[mt][2], a[mt][3],
                             b[nt][0], b[nt][1]);
        }
        __syncthreads();
        if (more) {
#pragma unroll
            for (int it = 0; it < 4; it++) {
                int4 v = pa[it];
                As[am + it * 64][ak + 0] = (v.x == 0) ? 1.f : 0.f;
                As[am + it * 64][ak + 1] = (v.y == 0) ? 1.f : 0.f;
                As[am + it * 64][ak + 2] = (v.z == 0) ? 1.f : 0.f;
                As[am + it * 64][ak + 3] = (v.w == 0) ? 1.f : 0.f;
            }
            *(float4*)&Bs[bk][bn] = pb0;
            *(float4*)&Bs[bk][bn + 4] = pb1;
        }
        __syncthreads();
    }

    // epilogue: scale by invcnt, add bias, write final output
#pragma unroll
    for (int mt = 0; mt < 4; mt++) {
        int r0a = row0 + wm + mt * 16 + gid;
        float s0 = g_invcnt[r0a];
        float s1 = g_invcnt[r0a + 8];
#pragma unroll
        for (int nt = 0; nt < 8; nt++) {
            int col = e0 + wn + nt * 8 + 2 * tig;
            float b0v = bo[col], b1v = bo[col + 1];
            float2 v0 = make_float2(acc[mt][nt][0] * s0 + b0v, acc[mt][nt][1] * s0 + b1v);
            float2 v1 = make_float2(acc[mt][nt][2] * s1 + b0v, acc[mt][nt][3] * s1 + b1v);
            *(float2*)(Y + (long)r0a * EMB + col) = v0;
            *(float2*)(Y + (long)(r0a + 8) * EMB + col) = v1;
        }
    }
}

// ---------------------------------------------------------------------------
extern "C" void kernel_launch(void* const* d_in, const int* in_sizes, int n_in,
                              void* d_out, int out_size)
{
    const float* value = (const float*)d_in[0];
    // d_in[1] = key, d_in[2] = query: unused — masked_fill(+1e20) before softmax
    // makes every unmasked score underflow to 0; output is the masked average.
    const int*   mask  = (const int*)d_in[3];
    const float* Wv    = (const float*)d_in[4];
    // d_in[5] = Wk, d_in[6] = Wq: unused
    const float* Wo    = (const float*)d_in[7];
    const float* bo    = (const float*)d_in[8];
    float* out = (float*)d_out;

    // 1) fold Wv/Wo -> Wcomb (tiny)
    {
        dim3 grid(NHEADS, EMB / 64);
        wcomb_kernel<<<grid, 256>>>(Wv, Wo);
    }
    // 2) per-row zero counts
    count_kernel<<<NB * SEQ, 256>>>(mask);
    // 3) Vc = value @ Wcomb   (tf32 tensor cores)
    {
        dim3 grid(EMB / BN, NB * SEQ / BM);
        vc_gemm_kernel<<<grid, 256>>>(value);
    }
    // 4) out = diag(invcnt) * (M0 @ Vc) + bo   (tf32 tensor cores)
    {
        dim3 grid(EMB / BN, NB * SEQ / BM);
        masked_gemm_kernel<<<grid, 256>>>(mask, bo, out);
    }
}

// round 4
// speedup vs baseline: 14.7466x; 1.4005x over previous
#include <cuda_runtime.h>
#include <cstdint>

#define NB 2
#define SEQ 2048
#define EMB 1024
#define NHEADS 16

// Scratch (__device__ globals per allocation rules)
__device__ float g_wcomb[EMB * EMB];       // folded Wv/Wo: [k'][n], tf32-rounded
__device__ float g_vc[NB * SEQ * EMB];     // V @ Wcomb, tf32-rounded
__device__ float g_invcnt[NB * SEQ];       // 1 / (# zeros in mask row)

// ---------------------------------------------------------------------------
__device__ __forceinline__ float to_tf32(float x) {
    uint32_t u;
    asm("cvt.rna.tf32.f32 %0, %1;" : "=r"(u) : "f"(x));
    return __uint_as_float(u);
}

__device__ __forceinline__ void mma_tf32(float c[4],
                                         uint32_t a0, uint32_t a1, uint32_t a2, uint32_t a3,
                                         uint32_t b0, uint32_t b1) {
    asm volatile(
        "mma.sync.aligned.m16n8k8.row.col.f32.tf32.tf32.f32 "
        "{%0,%1,%2,%3}, {%4,%5,%6,%7}, {%8,%9}, {%0,%1,%2,%3};"
        : "+f"(c[0]), "+f"(c[1]), "+f"(c[2]), "+f"(c[3])
        : "r"(a0), "r"(a1), "r"(a2), "r"(a3), "r"(b0), "r"(b1));
}

__device__ __forceinline__ void cp16(uint32_t s, const void* g) {
    asm volatile("cp.async.cg.shared.global [%0], [%1], 16;" :: "r"(s), "l"(g));
}
__device__ __forceinline__ void cp_commit() { asm volatile("cp.async.commit_group;"); }
__device__ __forceinline__ void cp_wait0()  { asm volatile("cp.async.wait_group 0;"); }

// ---------------------------------------------------------------------------
// Kernel 1: Wcomb[h*64+d'][n] = sum_d Wv[d][d'] * Wo[n][h*64+d]
// ---------------------------------------------------------------------------
__global__ __launch_bounds__(256) void wcomb_kernel(
    const float* __restrict__ Wv, const float* __restrict__ Wo)
{
    __shared__ float sWv[64][68];
    __shared__ float sWoT[64][68];

    const int h = blockIdx.x;
    const int n0 = blockIdx.y * 64;
    const int tid = threadIdx.x;

    for (int i = tid; i < 4096; i += 256) {
        int d = i >> 6, r = i & 63;
        sWv[d][r] = Wv[i];
    }
    for (int i = tid; i < 4096; i += 256) {
        int c = i >> 6, d = i & 63;
        sWoT[d][c] = Wo[(long)(n0 + c) * EMB + h * 64 + d];
    }
    __syncthreads();

    const int tr = (tid >> 4) * 4, tc = (tid & 15) * 4;
    float acc[4][4];
#pragma unroll
    for (int i = 0; i < 4; i++)
#pragma unroll
        for (int j = 0; j < 4; j++) acc[i][j] = 0.f;

#pragma unroll
    for (int d = 0; d < 64; d++) {
        float4 av = *(const float4*)&sWv[d][tr];
        float4 bv = *(const float4*)&sWoT[d][tc];
        float a[4] = {av.x, av.y, av.z, av.w};
        float b[4] = {bv.x, bv.y, bv.z, bv.w};
#pragma unroll
        for (int i = 0; i < 4; i++)
#pragma unroll
            for (int j = 0; j < 4; j++) acc[i][j] += a[i] * b[j];
    }

#pragma unroll
    for (int i = 0; i < 4; i++) {
        float4 v = make_float4(to_tf32(acc[i][0]), to_tf32(acc[i][1]),
                               to_tf32(acc[i][2]), to_tf32(acc[i][3]));
        *(float4*)(g_wcomb + (long)(h * 64 + tr + i) * EMB + n0 + tc) = v;
    }
}

// ---------------------------------------------------------------------------
// Kernel 2: per-row zero counts -> 1/count
// ---------------------------------------------------------------------------
__global__ __launch_bounds__(256) void count_kernel(const int* __restrict__ mask)
{
    const int tid = threadIdx.x;
    const long base = (long)blockIdx.x * SEQ;
    const int4* mp = (const int4*)(mask + base);

    int c = 0;
    int4 a = mp[tid];
    c += (a.x == 0) + (a.y == 0) + (a.z == 0) + (a.w == 0);
    int4 b = mp[tid + 256];
    c += (b.x == 0) + (b.y == 0) + (b.z == 0) + (b.w == 0);

#pragma unroll
    for (int off = 16; off > 0; off >>= 1)
        c += __shfl_down_sync(0xffffffffu, c, off);

    __shared__ int ws[8];
    if ((tid & 31) == 0) ws[tid >> 5] = c;
    __syncthreads();
    if (tid == 0) {
        int t = 0;
#pragma unroll
        for (int i = 0; i < 8; i++) t += ws[i];
        g_invcnt[blockIdx.x] = 1.0f / (float)t;
    }
}

// ---------------------------------------------------------------------------
// GEMM config: block 128x128, BK=16, 8 warps (2m x 4n), warp tile 64x32,
// cp.async double-buffered smem, 2 CTAs/SM.
// ---------------------------------------------------------------------------
#define BM 128
#define BN 128
#define BK 16
#define APAD 20
#define BPAD 136

// Kernel 3: Vc = value @ Wcomb (A cvt->tf32 in regs; B pre-rounded)
__global__ __launch_bounds__(256, 2) void vc_gemm_kernel(const float* __restrict__ V)
{
    __shared__ float As[2][BM][APAD];
    __shared__ float Bs[2][BK][BPAD];

    const int tid = threadIdx.x;
    const int wid = tid >> 5, lane = tid & 31;
    const int gid = lane >> 2, tig = lane & 3;
    const int wm = (wid >> 2) * 64;
    const int wn = (wid & 3) * 32;

    const int e0 = blockIdx.x * BN;
    const int row0 = blockIdx.y * BM;

    float acc[4][4][4];
#pragma unroll
    for (int a = 0; a < 4; a++)
#pragma unroll
        for (int b = 0; b < 4; b++)
#pragma unroll
            for (int c = 0; c < 4; c++) acc[a][b][c] = 0.f;

    // loader mapping: A chunks c = tid + i*256 (i<2): row=c>>2, col4=(c&3)*4
    const int ar = tid >> 2, ac = (tid & 3) * 4;
    const int br = tid >> 5, bc = (tid & 31) * 4;   // B: brow=c>>5, bcol4=(c&31)*4

    const float* Abase = V + (long)row0 * EMB;

    uint32_t sA0 = (uint32_t)__cvta_generic_to_shared(&As[0][0][0]);
    uint32_t sB0 = (uint32_t)__cvta_generic_to_shared(&Bs[0][0][0]);
    const uint32_t aStage = BM * APAD * 4;
    const uint32_t bStage = BK * BPAD * 4;

#define LOAD_TILE_VC(k0, st) do {                                                  \
        cp16(sA0 + (st) * aStage + ((ar) * APAD + ac) * 4,                         \
             Abase + (long)ar * EMB + (k0) + ac);                                  \
        cp16(sA0 + (st) * aStage + ((ar + 64) * APAD + ac) * 4,                    \
             Abase + (long)(ar + 64) * EMB + (k0) + ac);                           \
        cp16(sB0 + (st) * bStage + ((br) * BPAD + bc) * 4,                         \
             g_wcomb + (long)((k0) + br) * EMB + e0 + bc);                         \
        cp16(sB0 + (st) * bStage + ((br + 8) * BPAD + bc) * 4,                     \
             g_wcomb + (long)((k0) + br + 8) * EMB + e0 + bc);                     \
        cp_commit();                                                               \
    } while (0)

    LOAD_TILE_VC(0, 0);

    const int nIter = EMB / BK;
    for (int i = 0; i < nIter; i++) {
        cp_wait0();
        __syncthreads();
        if (i + 1 < nIter) LOAD_TILE_VC((i + 1) * BK, (i + 1) & 1);

        const int st = i & 1;
#pragma unroll
        for (int ks = 0; ks < 2; ks++) {
            const int kk = ks * 8;
            uint32_t a[4][4], b[4][2];
#pragma unroll
            for (int mt = 0; mt < 4; mt++) {
                int m = wm + mt * 16;
                a[mt][0] = __float_as_uint(to_tf32(As[st][m + gid][kk + tig]));
                a[mt][1] = __float_as_uint(to_tf32(As[st][m + gid + 8][kk + tig]));
                a[mt][2] = __float_as_uint(to_tf32(As[st][m + gid][kk + tig + 4]));
                a[mt][3] = __float_as_uint(to_tf32(As[st][m + gid + 8][kk + tig + 4]));
            }
#pragma unroll
            for (int nt = 0; nt < 4; nt++) {
                int nn = wn + nt * 8;
                b[nt][0] = __float_as_uint(Bs[st][kk + tig][nn + gid]);
                b[nt][1] = __float_as_uint(Bs[st][kk + tig + 4][nn + gid]);
            }
#pragma unroll
            for (int mt = 0; mt < 4; mt++)
#pragma unroll
                for (int nt = 0; nt < 4; nt++)
                    mma_tf32(acc[mt][nt], a[mt][0], a[mt][1], a[mt][2], a[mt][3],
                             b[nt][0], b[nt][1]);
        }
        __syncthreads();
    }

    // epilogue: tf32-round and store Vc
#pragma unroll
    for (int mt = 0; mt < 4; mt++) {
        int r0a = row0 + wm + mt * 16 + gid;
#pragma unroll
        for (int nt = 0; nt < 4; nt++) {
            int col = e0 + wn + nt * 8 + 2 * tig;
            float2 v0 = make_float2(to_tf32(acc[mt][nt][0]), to_tf32(acc[mt][nt][1]));
            float2 v1 = make_float2(to_tf32(acc[mt][nt][2]), to_tf32(acc[mt][nt][3]));
            *(float2*)(g_vc + (long)r0a * EMB + col) = v0;
            *(float2*)(g_vc + (long)(r0a + 8) * EMB + col) = v1;
        }
    }
}

// Kernel 4: out[row] = sum_k (mask[row,k]==0 ? invcnt[row] : 0) * Vc[k] + bo
// A built from raw mask ints at fragment-load time (invcnt folded in).
__global__ __launch_bounds__(256, 2) void masked_gemm_kernel(
    const int* __restrict__ mask, const float* __restrict__ bo, float* __restrict__ Y)
{
    __shared__ int   As[2][BM][APAD];
    __shared__ float Bs[2][BK][BPAD];

    const int tid = threadIdx.x;
    const int wid = tid >> 5, lane = tid & 31;
    const int gid = lane >> 2, tig = lane & 3;
    const int wm = (wid >> 2) * 64;
    const int wn = (wid & 3) * 32;

    const int e0 = blockIdx.x * BN;
    const int row0 = blockIdx.y * BM;
    const int n = row0 / SEQ;

    const int* mbase = mask + (long)n * SEQ * SEQ + (long)(row0 % SEQ) * SEQ;
    const float* vbase = g_vc + (long)n * SEQ * EMB;

    // per-warp invcnt values (tf32-rounded, folded into A)
    float inv0[4], inv1[4];
#pragma unroll
    for (int mt = 0; mt < 4; mt++) {
        inv0[mt] = to_tf32(g_invcnt[row0 + wm + mt * 16 + gid]);
        inv1[mt] = to_tf32(g_invcnt[row0 + wm + mt * 16 + gid + 8]);
    }

    float acc[4][4][4];
#pragma unroll
    for (int a = 0; a < 4; a++)
#pragma unroll
        for (int b = 0; b < 4; b++)
#pragma unroll
            for (int c = 0; c < 4; c++) acc[a][b][c] = 0.f;

    const int ar = tid >> 2, ac = (tid & 3) * 4;
    const int br = tid >> 5, bc = (tid & 31) * 4;

    uint32_t sA0 = (uint32_t)__cvta_generic_to_shared(&As[0][0][0]);
    uint32_t sB0 = (uint32_t)__cvta_generic_to_shared(&Bs[0][0][0]);
    const uint32_t aStage = BM * APAD * 4;
    const uint32_t bStage = BK * BPAD * 4;

#define LOAD_TILE_MS(k0, st) do {                                                  \
        cp16(sA0 + (st) * aStage + ((ar) * APAD + ac) * 4,                         \
             mbase + (long)ar * SEQ + (k0) + ac);                                  \
        cp16(sA0 + (st) * aStage + ((ar + 64) * APAD + ac) * 4,                    \
             mbase + (long)(ar + 64) * SEQ + (k0) + ac);                           \
        cp16(sB0 + (st) * bStage + ((br) * BPAD + bc) * 4,                         \
             vbase + (long)((k0) + br) * EMB + e0 + bc);                           \
        cp16(sB0 + (st) * bStage + ((br + 8) * BPAD + bc) * 4,                     \
             vbase + (long)((k0) + br + 8) * EMB + e0 + bc);                       \
        cp_commit();                                                               \
    } while (0)

    LOAD_TILE_MS(0, 0);

    const int nIter = SEQ / BK;
    for (int i = 0; i < nIter; i++) {
        cp_wait0();
        __syncthreads();
        if (i + 1 < nIter) LOAD_TILE_MS((i + 1) * BK, (i + 1) & 1);

        const int st = i & 1;
#pragma unroll
        for (int ks = 0; ks < 2; ks++) {
            const int kk = ks * 8;
            uint32_t a[4][4], b[4][2];
#pragma unroll
            for (int mt = 0; mt < 4; mt++) {
                int m = wm + mt * 16;
                a[mt][0] = __float_as_uint(As[st][m + gid][kk + tig] == 0 ? inv0[mt] : 0.f);
                a[mt][1] = __float_as_uint(As[st][m + gid + 8][kk + tig] == 0 ? inv1[mt] : 0.f);
                a[mt][2] = __float_as_uint(As[st][m + gid][kk + tig + 4] == 0 ? inv0[mt] : 0.f);
                a[mt][3] = __float_as_uint(As[st][m + gid + 8][kk + tig + 4] == 0 ? inv1[mt] : 0.f);
            }
#pragma unroll
            for (int nt = 0; nt < 4; nt++) {
                int nn = wn + nt * 8;
                b[nt][0] = __float_as_uint(Bs[st][kk + tig][nn + gid]);
                b[nt][1] = __float_as_uint(Bs[st][kk + tig + 4][nn + gid]);
            }
#pragma unroll
            for (int mt = 0; mt < 4; mt++)
#pragma unroll
                for (int nt = 0; nt < 4; nt++)
                    mma_tf32(acc[mt][nt], a[mt][0], a[mt][1], a[mt][2], a[mt][3],
                             b[nt][0], b[nt][1]);
        }
        __syncthreads();
    }

    // epilogue: + bias (invcnt already folded into A)
#pragma unroll
    for (int mt = 0; mt < 4; mt++) {
        int r0a = row0 + wm + mt * 16 + gid;
#pragma unroll
        for (int nt = 0; nt < 4; nt++) {
            int col = e0 + wn + nt * 8 + 2 * tig;
            float b0v = bo[col], b1v = bo[col + 1];
            float2 v0 = make_float2(acc[mt][nt][0] + b0v, acc[mt][nt][1] + b1v);
            float2 v1 = make_float2(acc[mt][nt][2] + b0v, acc[mt][nt][3] + b1v);
            *(float2*)(Y + (long)r0a * EMB + col) = v0;
            *(float2*)(Y + (long)(r0a + 8) * EMB + col) = v1;
        }
    }
}

// ---------------------------------------------------------------------------
extern "C" void kernel_launch(void* const* d_in, const int* in_sizes, int n_in,
                              void* d_out, int out_size)
{
    const float* value = (const float*)d_in[0];
    // key/query/Wk/Wq unused: masked_fill(+1e20) before softmax forces all
    // unmasked scores to underflow; output is the masked average of projected V.
    const int*   mask  = (const int*)d_in[3];
    const float* Wv    = (const float*)d_in[4];
    const float* Wo    = (const float*)d_in[7];
    const float* bo    = (const float*)d_in[8];
    float* out = (float*)d_out;

    {
        dim3 grid(NHEADS, EMB / 64);
        wcomb_kernel<<<grid, 256>>>(Wv, Wo);
    }
    count_kernel<<<NB * SEQ, 256>>>(mask);
    {
        dim3 grid(EMB / BN, NB * SEQ / BM);
        vc_gemm_kernel<<<grid, 256>>>(value);
    }
    {
        dim3 grid(EMB / BN, NB * SEQ / BM);
        masked_gemm_kernel<<<grid, 256>>>(mask, bo, out);
    }
}

// round 6
// speedup vs baseline: 16.3943x; 1.1117x over previous
#include <cuda_runtime.h>
#include <cstdint>

#define NB 2
#define SEQ 2048
#define EMB 1024
#define NHEADS 16

// Scratch (__device__ globals per allocation rules)
__device__ float g_wcomb[EMB * EMB];       // folded Wv/Wo: [k'][n], tf32-rounded
__device__ float g_vc[NB * SEQ * EMB];     // V @ Wcomb, tf32-rounded
__device__ float g_af[NB * SEQ * SEQ];     // mask as scaled tf32: invcnt[row] or 0

// ---------------------------------------------------------------------------
__device__ __forceinline__ float to_tf32(float x) {
    uint32_t u;
    asm("cvt.rna.tf32.f32 %0, %1;" : "=r"(u) : "f"(x));
    return __uint_as_float(u);
}

__device__ __forceinline__ void mma_tf32(float c[4],
                                         uint32_t a0, uint32_t a1, uint32_t a2, uint32_t a3,
                                         uint32_t b0, uint32_t b1) {
    asm volatile(
        "mma.sync.aligned.m16n8k8.row.col.f32.tf32.tf32.f32 "
        "{%0,%1,%2,%3}, {%4,%5,%6,%7}, {%8,%9}, {%0,%1,%2,%3};"
        : "+f"(c[0]), "+f"(c[1]), "+f"(c[2]), "+f"(c[3])
        : "r"(a0), "r"(a1), "r"(a2), "r"(a3), "r"(b0), "r"(b1));
}

__device__ __forceinline__ void cp16(uint32_t s, const void* g) {
    asm volatile("cp.async.cg.shared.global [%0], [%1], 16;" :: "r"(s), "l"(g));
}
__device__ __forceinline__ void cp_commit() { asm volatile("cp.async.commit_group;"); }
__device__ __forceinline__ void cp_wait0()  { asm volatile("cp.async.wait_group 0;"); }

// ---------------------------------------------------------------------------
// Kernel 1: Wcomb[h*64+d'][n] = sum_d Wv[d][d'] * Wo[n][h*64+d]
// ---------------------------------------------------------------------------
__global__ __launch_bounds__(256) void wcomb_kernel(
    const float* __restrict__ Wv, const float* __restrict__ Wo)
{
    __shared__ float sWv[64][68];
    __shared__ float sWoT[64][68];

    const int h = blockIdx.x;
    const int n0 = blockIdx.y * 64;
    const int tid = threadIdx.x;

    for (int i = tid; i < 4096; i += 256) {
        int d = i >> 6, r = i & 63;
        sWv[d][r] = Wv[i];
    }
    for (int i = tid; i < 4096; i += 256) {
        int c = i >> 6, d = i & 63;
        sWoT[d][c] = Wo[(long)(n0 + c) * EMB + h * 64 + d];
    }
    __syncthreads();

    const int tr = (tid >> 4) * 4, tc = (tid & 15) * 4;
    float acc[4][4];
#pragma unroll
    for (int i = 0; i < 4; i++)
#pragma unroll
        for (int j = 0; j < 4; j++) acc[i][j] = 0.f;

#pragma unroll
    for (int d = 0; d < 64; d++) {
        float4 av = *(const float4*)&sWv[d][tr];
        float4 bv = *(const float4*)&sWoT[d][tc];
        float a[4] = {av.x, av.y, av.z, av.w};
        float b[4] = {bv.x, bv.y, bv.z, bv.w};
#pragma unroll
        for (int i = 0; i < 4; i++)
#pragma unroll
            for (int j = 0; j < 4; j++) acc[i][j] += a[i] * b[j];
    }

#pragma unroll
    for (int i = 0; i < 4; i++) {
        float4 v = make_float4(to_tf32(acc[i][0]), to_tf32(acc[i][1]),
                               to_tf32(acc[i][2]), to_tf32(acc[i][3]));
        *(float4*)(g_wcomb + (long)(h * 64 + tr + i) * EMB + n0 + tc) = v;
    }
}

// ---------------------------------------------------------------------------
// Kernel 2: count zeros per mask row, write g_af = (mask==0 ? tf32(1/cnt) : 0)
// ---------------------------------------------------------------------------
__global__ __launch_bounds__(256) void maskf_kernel(const int* __restrict__ mask)
{
    const int tid = threadIdx.x;
    const long base = (long)blockIdx.x * SEQ;
    const int4* mp = (const int4*)(mask + base);

    int4 a = mp[tid];
    int4 b = mp[tid + 256];
    int c = (a.x == 0) + (a.y == 0) + (a.z == 0) + (a.w == 0)
          + (b.x == 0) + (b.y == 0) + (b.z == 0) + (b.w == 0);

#pragma unroll
    for (int off = 16; off > 0; off >>= 1)
        c += __shfl_down_sync(0xffffffffu, c, off);

    __shared__ int ws[8];
    __shared__ float s_inv;
    if ((tid & 31) == 0) ws[tid >> 5] = c;
    __syncthreads();
    if (tid == 0) {
        int t = 0;
#pragma unroll
        for (int i = 0; i < 8; i++) t += ws[i];
        s_inv = to_tf32(1.0f / (float)t);
    }
    __syncthreads();
    const float inv = s_inv;

    float4* fp = (float4*)(g_af + base);
    float4 f0, f1;
    f0.x = (a.x == 0) ? inv : 0.f; f0.y = (a.y == 0) ? inv : 0.f;
    f0.z = (a.z == 0) ? inv : 0.f; f0.w = (a.w == 0) ? inv : 0.f;
    f1.x = (b.x == 0) ? inv : 0.f; f1.y = (b.y == 0) ? inv : 0.f;
    f1.z = (b.z == 0) ? inv : 0.f; f1.w = (b.w == 0) ? inv : 0.f;
    fp[tid] = f0;
    fp[tid + 256] = f1;
}

// ---------------------------------------------------------------------------
// GEMM config: block 128x128, BK=32, 8 warps (2m x 4n), warp tile 64x32,
// XOR-swizzled smem (no padding), cp.async double buffer, 2 CTAs/SM.
// Dynamic smem: 2*(128*32 + 32*128)*4 = 64KB.
// ---------------------------------------------------------------------------
#define BM 128
#define BN 128
#define BK 32
#define A_STG (BM * BK)
#define B_STG (BK * BN)
#define GSMEM_BYTES (2 * (A_STG + B_STG) * 4)

// swizzles (float-index space); XOR bits never touch bits 0-1 (16B chunks intact)
#define ASW(r, c) (((r) * BK) + ((c) ^ (((r) & 7) << 2)))
#define BSW(r, c) (((r) * BN) + ((c) ^ (((r) & 3) << 3)))

// Parameterized tile loader (function, NOT macro: k0/st evaluate at call site).
// Ab: A base (row stride = astride), Bb: B base pre-offset by e0 (row stride EMB).
__device__ __forceinline__ void gemm_load(uint32_t sA, uint32_t sB,
                                          const float* Ab, long astride,
                                          const float* Bb, int tid, int k0, int st)
{
#pragma unroll
    for (int u = 0; u < 4; u++) {
        int ch = tid + u * 256;
        int r = ch >> 3, c4 = (ch & 7) * 4;
        cp16(sA + (uint32_t)(st * A_STG + ASW(r, c4)) * 4,
             Ab + (long)r * astride + k0 + c4);
    }
#pragma unroll
    for (int u = 0; u < 4; u++) {
        int ch = tid + u * 256;
        int r = ch >> 5, c4 = (ch & 31) * 4;
        cp16(sB + (uint32_t)(st * B_STG + BSW(r, c4)) * 4,
             Bb + (long)(k0 + r) * EMB + c4);
    }
    cp_commit();
}

// Kernel 3: Vc = value @ Wcomb (A cvt->tf32 at fragment; B pre-rounded)
__global__ __launch_bounds__(256, 2) void vc_gemm_kernel(const float* __restrict__ V)
{
    extern __shared__ float sm[];
    float* As = sm;
    float* Bs = sm + 2 * A_STG;

    const int tid = threadIdx.x;
    const int wid = tid >> 5, lane = tid & 31;
    const int gid = lane >> 2, tig = lane & 3;
    const int wm = (wid >> 2) * 64;
    const int wn = (wid & 3) * 32;

    const int e0 = blockIdx.x * BN;
    const int row0 = blockIdx.y * BM;

    float acc[4][4][4];
#pragma unroll
    for (int a = 0; a < 4; a++)
#pragma unroll
        for (int b = 0; b < 4; b++)
#pragma unroll
            for (int c = 0; c < 4; c++) acc[a][b][c] = 0.f;

    const float* Abase = V + (long)row0 * EMB;
    const float* Bbase = g_wcomb + e0;
    uint32_t sA = (uint32_t)__cvta_generic_to_shared(As);
    uint32_t sB = (uint32_t)__cvta_generic_to_shared(Bs);

    gemm_load(sA, sB, Abase, EMB, Bbase, tid, 0, 0);

    const int nIter = EMB / BK;
    for (int i = 0; i < nIter; i++) {
        cp_wait0();
        __syncthreads();
        if (i + 1 < nIter)
            gemm_load(sA, sB, Abase, EMB, Bbase, tid, (i + 1) * BK, (i + 1) & 1);

        const int st = i & 1;
        const float* Ast = As + st * A_STG;
        const float* Bst = Bs + st * B_STG;
#pragma unroll
        for (int ks = 0; ks < 4; ks++) {
            const int kk = ks * 8;
            uint32_t a[4][4], b[4][2];
#pragma unroll
            for (int mt = 0; mt < 4; mt++) {
                int m = wm + mt * 16;
                a[mt][0] = __float_as_uint(to_tf32(Ast[ASW(m + gid,     kk + tig)]));
                a[mt][1] = __float_as_uint(to_tf32(Ast[ASW(m + gid + 8, kk + tig)]));
                a[mt][2] = __float_as_uint(to_tf32(Ast[ASW(m + gid,     kk + tig + 4)]));
                a[mt][3] = __float_as_uint(to_tf32(Ast[ASW(m + gid + 8, kk + tig + 4)]));
            }
#pragma unroll
            for (int nt = 0; nt < 4; nt++) {
                int nn = wn + nt * 8;
                b[nt][0] = __float_as_uint(Bst[BSW(kk + tig,     nn + gid)]);
                b[nt][1] = __float_as_uint(Bst[BSW(kk + tig + 4, nn + gid)]);
            }
#pragma unroll
            for (int mt = 0; mt < 4; mt++)
#pragma unroll
                for (int nt = 0; nt < 4; nt++)
                    mma_tf32(acc[mt][nt], a[mt][0], a[mt][1], a[mt][2], a[mt][3],
                             b[nt][0], b[nt][1]);
        }
        __syncthreads();
    }

#pragma unroll
    for (int mt = 0; mt < 4; mt++) {
        int r0a = row0 + wm + mt * 16 + gid;
#pragma unroll
        for (int nt = 0; nt < 4; nt++) {
            int col = e0 + wn + nt * 8 + 2 * tig;
            float2 v0 = make_float2(to_tf32(acc[mt][nt][0]), to_tf32(acc[mt][nt][1]));
            float2 v1 = make_float2(to_tf32(acc[mt][nt][2]), to_tf32(acc[mt][nt][3]));
            *(float2*)(g_vc + (long)r0a * EMB + col) = v0;
            *(float2*)(g_vc + (long)(r0a + 8) * EMB + col) = v1;
        }
    }
}

// Kernel 4: out = g_af @ Vc + bo   (pure tf32 GEMM; invcnt pre-folded in g_af)
__global__ __launch_bounds__(256, 2) void masked_gemm_kernel(
    const float* __restrict__ bo, float* __restrict__ Y)
{
    extern __shared__ float sm[];
    float* As = sm;
    float* Bs = sm + 2 * A_STG;

    const int tid = threadIdx.x;
    const int wid = tid >> 5, lane = tid & 31;
    const int gid = lane >> 2, tig = lane & 3;
    const int wm = (wid >> 2) * 64;
    const int wn = (wid & 3) * 32;

    const int e0 = blockIdx.x * BN;
    const int row0 = blockIdx.y * BM;
    const int n = row0 / SEQ;

    const float* Abase = g_af + (long)row0 * SEQ;
    const float* Bbase = g_vc + (long)n * SEQ * EMB + e0;

    float acc[4][4][4];
#pragma unroll
    for (int a = 0; a < 4; a++)
#pragma unroll
        for (int b = 0; b < 4; b++)
#pragma unroll
            for (int c = 0; c < 4; c++) acc[a][b][c] = 0.f;

    uint32_t sA = (uint32_t)__cvta_generic_to_shared(As);
    uint32_t sB = (uint32_t)__cvta_generic_to_shared(Bs);

    gemm_load(sA, sB, Abase, SEQ, Bbase, tid, 0, 0);

    const int nIter = SEQ / BK;
    for (int i = 0; i < nIter; i++) {
        cp_wait0();
        __syncthreads();
        if (i + 1 < nIter)
            gemm_load(sA, sB, Abase, SEQ, Bbase, tid, (i + 1) * BK, (i + 1) & 1);

        const int st = i & 1;
        const float* Ast = As + st * A_STG;
        const float* Bst = Bs + st * B_STG;
#pragma unroll
        for (int ks = 0; ks < 4; ks++) {
            const int kk = ks * 8;
            uint32_t a[4][4], b[4][2];
#pragma unroll
            for (int mt = 0; mt < 4; mt++) {
                int m = wm + mt * 16;
                a[mt][0] = __float_as_uint(Ast[ASW(m + gid,     kk + tig)]);
                a[mt][1] = __float_as_uint(Ast[ASW(m + gid + 8, kk + tig)]);
                a[mt][2] = __float_as_uint(Ast[ASW(m + gid,     kk + tig + 4)]);
                a[mt][3] = __float_as_uint(Ast[ASW(m + gid + 8, kk + tig + 4)]);
            }
#pragma unroll
            for (int nt = 0; nt < 4; nt++) {
                int nn = wn + nt * 8;
                b[nt][0] = __float_as_uint(Bst[BSW(kk + tig,     nn + gid)]);
                b[nt][1] = __float_as_uint(Bst[BSW(kk + tig + 4, nn + gid)]);
            }
#pragma unroll
            for (int mt = 0; mt < 4; mt++)
#pragma unroll
                for (int nt = 0; nt < 4; nt++)
                    mma_tf32(acc[mt][nt], a[mt][0], a[mt][1], a[mt][2], a[mt][3],
                             b[nt][0], b[nt][1]);
        }
        __syncthreads();
    }

#pragma unroll
    for (int mt = 0; mt < 4; mt++) {
        int r0a = row0 + wm + mt * 16 + gid;
#pragma unroll
        for (int nt = 0; nt < 4; nt++) {
            int col = e0 + wn + nt * 8 + 2 * tig;
            float b0v = bo[col], b1v = bo[col + 1];
            float2 v0 = make_float2(acc[mt][nt][0] + b0v, acc[mt][nt][1] + b1v);
            float2 v1 = make_float2(acc[mt][nt][2] + b0v, acc[mt][nt][3] + b1v);
            *(float2*)(Y + (long)r0a * EMB + col) = v0;
            *(float2*)(Y + (long)(r0a + 8) * EMB + col) = v1;
        }
    }
}

// ---------------------------------------------------------------------------
extern "C" void kernel_launch(void* const* d_in, const int* in_sizes, int n_in,
                              void* d_out, int out_size)
{
    const float* value = (const float*)d_in[0];
    // key/query/Wk/Wq unused: masked_fill(+1e20) before softmax forces all
    // unmasked scores to underflow; output is the masked average of projected V.
    const int*   mask  = (const int*)d_in[3];
    const float* Wv    = (const float*)d_in[4];
    const float* Wo    = (const float*)d_in[7];
    const float* bo    = (const float*)d_in[8];
    float* out = (float*)d_out;

    cudaFuncSetAttribute(vc_gemm_kernel,
                         cudaFuncAttributeMaxDynamicSharedMemorySize, GSMEM_BYTES);
    cudaFuncSetAttribute(masked_gemm_kernel,
                         cudaFuncAttributeMaxDynamicSharedMemorySize, GSMEM_BYTES);

    {
        dim3 grid(NHEADS, EMB / 64);
        wcomb_kernel<<<grid, 256>>>(Wv, Wo);
    }
    maskf_kernel<<<NB * SEQ, 256>>>(mask);
    {
        dim3 grid(EMB / BN, NB * SEQ / BM);
        vc_gemm_kernel<<<grid, 256, GSMEM_BYTES>>>(value);
    }
    {
        dim3 grid(EMB / BN, NB * SEQ / BM);
        masked_gemm_kernel<<<grid, 256, GSMEM_BYTES>>>(bo, out);
    }
}

// round 7
// speedup vs baseline: 17.0938x; 1.0427x over previous
#include <cuda_runtime.h>
#include <cstdint>

#define NB 2
#define SEQ 2048
#define EMB 1024
#define NHEADS 16

// Scratch (__device__ globals per allocation rules)
__device__ float g_wcomb[EMB * EMB];       // folded Wv/Wo: [k'][n], tf32-rounded
__device__ float g_vc[NB * SEQ * EMB];     // V @ Wcomb, tf32-rounded
__device__ float g_af[NB * SEQ * SEQ];     // mask as scaled tf32: invcnt[row] or 0

// ---------------------------------------------------------------------------
__device__ __forceinline__ float to_tf32(float x) {
    uint32_t u;
    asm("cvt.rna.tf32.f32 %0, %1;" : "=r"(u) : "f"(x));
    return __uint_as_float(u);
}
__device__ __forceinline__ uint32_t to_tf32_bits(uint32_t x) {
    uint32_t u;
    asm("cvt.rna.tf32.f32 %0, %1;" : "=r"(u) : "f"(__uint_as_float(x)));
    return u;
}

__device__ __forceinline__ void mma_tf32(float c[4],
                                         uint32_t a0, uint32_t a1, uint32_t a2, uint32_t a3,
                                         uint32_t b0, uint32_t b1) {
    asm volatile(
        "mma.sync.aligned.m16n8k8.row.col.f32.tf32.tf32.f32 "
        "{%0,%1,%2,%3}, {%4,%5,%6,%7}, {%8,%9}, {%0,%1,%2,%3};"
        : "+f"(c[0]), "+f"(c[1]), "+f"(c[2]), "+f"(c[3])
        : "r"(a0), "r"(a1), "r"(a2), "r"(a3), "r"(b0), "r"(b1));
}

__device__ __forceinline__ void ldsm_x4(uint32_t& a0, uint32_t& a1,
                                        uint32_t& a2, uint32_t& a3, uint32_t addr) {
    asm volatile("ldmatrix.sync.aligned.m8n8.x4.shared.b16 {%0,%1,%2,%3}, [%4];"
                 : "=r"(a0), "=r"(a1), "=r"(a2), "=r"(a3) : "r"(addr));
}

__device__ __forceinline__ void cp16(uint32_t s, const void* g) {
    asm volatile("cp.async.cg.shared.global [%0], [%1], 16;" :: "r"(s), "l"(g));
}
__device__ __forceinline__ void cp_commit() { asm volatile("cp.async.commit_group;"); }
__device__ __forceinline__ void cp_wait0()  { asm volatile("cp.async.wait_group 0;"); }
__device__ __forceinline__ void cp_wait1()  { asm volatile("cp.async.wait_group 1;"); }

// ---------------------------------------------------------------------------
// Kernel 1: Wcomb[h*64+d'][n] = sum_d Wv[d][d'] * Wo[n][h*64+d]
// ---------------------------------------------------------------------------
__global__ __launch_bounds__(256) void wcomb_kernel(
    const float* __restrict__ Wv, const float* __restrict__ Wo)
{
    __shared__ float sWv[64][68];
    __shared__ float sWoT[64][68];

    const int h = blockIdx.x;
    const int n0 = blockIdx.y * 64;
    const int tid = threadIdx.x;

    for (int i = tid; i < 4096; i += 256) {
        int d = i >> 6, r = i & 63;
        sWv[d][r] = Wv[i];
    }
    for (int i = tid; i < 4096; i += 256) {
        int c = i >> 6, d = i & 63;
        sWoT[d][c] = Wo[(long)(n0 + c) * EMB + h * 64 + d];
    }
    __syncthreads();

    const int tr = (tid >> 4) * 4, tc = (tid & 15) * 4;
    float acc[4][4];
#pragma unroll
    for (int i = 0; i < 4; i++)
#pragma unroll
        for (int j = 0; j < 4; j++) acc[i][j] = 0.f;

#pragma unroll
    for (int d = 0; d < 64; d++) {
        float4 av = *(const float4*)&sWv[d][tr];
        float4 bv = *(const float4*)&sWoT[d][tc];
        float a[4] = {av.x, av.y, av.z, av.w};
        float b[4] = {bv.x, bv.y, bv.z, bv.w};
#pragma unroll
        for (int i = 0; i < 4; i++)
#pragma unroll
            for (int j = 0; j < 4; j++) acc[i][j] += a[i] * b[j];
    }

#pragma unroll
    for (int i = 0; i < 4; i++) {
        float4 v = make_float4(to_tf32(acc[i][0]), to_tf32(acc[i][1]),
                               to_tf32(acc[i][2]), to_tf32(acc[i][3]));
        *(float4*)(g_wcomb + (long)(h * 64 + tr + i) * EMB + n0 + tc) = v;
    }
}

// ---------------------------------------------------------------------------
// Kernel 2: count zeros per mask row, write g_af = (mask==0 ? tf32(1/cnt) : 0)
// ---------------------------------------------------------------------------
__global__ __launch_bounds__(256) void maskf_kernel(const int* __restrict__ mask)
{
    const int tid = threadIdx.x;
    const long base = (long)blockIdx.x * SEQ;
    const int4* mp = (const int4*)(mask + base);

    int4 a = mp[tid];
    int4 b = mp[tid + 256];
    int c = (a.x == 0) + (a.y == 0) + (a.z == 0) + (a.w == 0)
          + (b.x == 0) + (b.y == 0) + (b.z == 0) + (b.w == 0);

#pragma unroll
    for (int off = 16; off > 0; off >>= 1)
        c += __shfl_down_sync(0xffffffffu, c, off);

    __shared__ int ws[8];
    __shared__ float s_inv;
    if ((tid & 31) == 0) ws[tid >> 5] = c;
    __syncthreads();
    if (tid == 0) {
        int t = 0;
#pragma unroll
        for (int i = 0; i < 8; i++) t += ws[i];
        s_inv = to_tf32(1.0f / (float)t);
    }
    __syncthreads();
    const float inv = s_inv;

    float4* fp = (float4*)(g_af + base);
    float4 f0, f1;
    f0.x = (a.x == 0) ? inv : 0.f; f0.y = (a.y == 0) ? inv : 0.f;
    f0.z = (a.z == 0) ? inv : 0.f; f0.w = (a.w == 0) ? inv : 0.f;
    f1.x = (b.x == 0) ? inv : 0.f; f1.y = (b.y == 0) ? inv : 0.f;
    f1.z = (b.z == 0) ? inv : 0.f; f1.w = (b.w == 0) ? inv : 0.f;
    fp[tid] = f0;
    fp[tid + 256] = f1;
}

// ---------------------------------------------------------------------------
// GEMM config: block 128x128, BK=32, 8 warps (2m x 4n), warp tile 64x32,
// XOR-swizzled smem, 3-stage cp.async pipeline, ldmatrix A fragments,
// one __syncthreads per iteration, 2 CTAs/SM.
// Dynamic smem: 3*(128*32 + 32*128)*4 = 96KB.
// ---------------------------------------------------------------------------
#define BM 128
#define BN 128
#define BK 32
#define A_STG (BM * BK)
#define B_STG (BK * BN)
#define NSTG 3
#define GSMEM_BYTES (NSTG * (A_STG + B_STG) * 4)

// swizzles (float-index space); XOR never touches bits 0-1 (16B chunks intact)
#define ASW(r, c) (((r) * BK) + ((c) ^ (((r) & 7) << 2)))
#define BSW(r, c) (((r) * BN) + ((c) ^ (((r) & 3) << 3)))

// Parameterized tile loader (function: k0/st evaluate at call site).
__device__ __forceinline__ void gemm_load(uint32_t sA, uint32_t sB,
                                          const float* Ab, long astride,
                                          const float* Bb, int tid, int k0, int st)
{
#pragma unroll
    for (int u = 0; u < 4; u++) {
        int ch = tid + u * 256;
        int r = ch >> 3, c4 = (ch & 7) * 4;
        cp16(sA + (uint32_t)(st * A_STG + ASW(r, c4)) * 4,
             Ab + (long)r * astride + k0 + c4);
    }
#pragma unroll
    for (int u = 0; u < 4; u++) {
        int ch = tid + u * 256;
        int r = ch >> 5, c4 = (ch & 31) * 4;
        cp16(sB + (uint32_t)(st * B_STG + BSW(r, c4)) * 4,
             Bb + (long)(k0 + r) * EMB + c4);
    }
    cp_commit();
}

// Shared GEMM core. CVT_A: convert A fragments to tf32 (for raw fp32 inputs).
template <bool CVT_A>
__device__ __forceinline__ void gemm_core(
    const float* Ab, long astride, const float* Bb,
    float acc[4][4][4], int nIter)
{
    extern __shared__ float sm[];
    float* As = sm;
    float* Bs = sm + NSTG * A_STG;

    const int tid = threadIdx.x;
    const int wid = tid >> 5, lane = tid & 31;
    const int gid = lane >> 2, tig = lane & 3;
    const int wm = (wid >> 2) * 64;
    const int wn = (wid & 3) * 32;

    uint32_t sA = (uint32_t)__cvta_generic_to_shared(As);
    uint32_t sB = (uint32_t)__cvta_generic_to_shared(Bs);

    // ldmatrix per-lane geometry: lanes 0-15 -> rows m..m+15 (k lo),
    // lanes 16-31 -> rows m..m+15 (k hi, +4 words)
    const int lrow = lane & 15;
    const int koff = (lane & 16) ? 4 : 0;
    int abase[4], aswz[4];
#pragma unroll
    for (int mt = 0; mt < 4; mt++) {
        int r = wm + mt * 16 + lrow;
        abase[mt] = r * BK;
        aswz[mt] = (r & 7) << 2;
    }

    gemm_load(sA, sB, Ab, astride, Bb, tid, 0, 0);
    gemm_load(sA, sB, Ab, astride, Bb, tid, BK, 1);

    for (int i = 0; i < nIter; i++) {
        if (i < nIter - 1) cp_wait1(); else cp_wait0();
        __syncthreads();
        if (i + 2 < nIter)
            gemm_load(sA, sB, Ab, astride, Bb, tid, (i + 2) * BK, (i + 2) % NSTG);

        const int st = i % NSTG;
        const uint32_t aOff = sA + (uint32_t)(st * A_STG) * 4;
        const float* Bst = Bs + st * B_STG;

#pragma unroll
        for (int ks = 0; ks < 4; ks++) {
            const int kk = ks * 8;
            uint32_t a[4][4], b[4][2];
#pragma unroll
            for (int mt = 0; mt < 4; mt++) {
                uint32_t addr = aOff +
                    (uint32_t)(abase[mt] + (((kk | koff)) ^ aswz[mt])) * 4;
                ldsm_x4(a[mt][0], a[mt][1], a[mt][2], a[mt][3], addr);
                if (CVT_A) {
                    a[mt][0] = to_tf32_bits(a[mt][0]);
                    a[mt][1] = to_tf32_bits(a[mt][1]);
                    a[mt][2] = to_tf32_bits(a[mt][2]);
                    a[mt][3] = to_tf32_bits(a[mt][3]);
                }
            }
#pragma unroll
            for (int nt = 0; nt < 4; nt++) {
                int nn = wn + nt * 8;
                b[nt][0] = __float_as_uint(Bst[BSW(kk + tig,     nn + gid)]);
                b[nt][1] = __float_as_uint(Bst[BSW(kk + tig + 4, nn + gid)]);
            }
#pragma unroll
            for (int mt = 0; mt < 4; mt++)
#pragma unroll
                for (int nt = 0; nt < 4; nt++)
                    mma_tf32(acc[mt][nt], a[mt][0], a[mt][1], a[mt][2], a[mt][3],
                             b[nt][0], b[nt][1]);
        }
    }
}

// Kernel 3: Vc = value @ Wcomb (A cvt->tf32 at fragment; B pre-rounded)
__global__ __launch_bounds__(256, 2) void vc_gemm_kernel(const float* __restrict__ V)
{
    const int tid = threadIdx.x;
    const int wid = tid >> 5, lane = tid & 31;
    const int gid = lane >> 2, tig = lane & 3;
    const int wm = (wid >> 2) * 64;
    const int wn = (wid & 3) * 32;

    const int e0 = blockIdx.x * BN;
    const int row0 = blockIdx.y * BM;

    float acc[4][4][4];
#pragma unroll
    for (int a = 0; a < 4; a++)
#pragma unroll
        for (int b = 0; b < 4; b++)
#pragma unroll
            for (int c = 0; c < 4; c++) acc[a][b][c] = 0.f;

    gemm_core<true>(V + (long)row0 * EMB, EMB, g_wcomb + e0, acc, EMB / BK);

#pragma unroll
    for (int mt = 0; mt < 4; mt++) {
        int r0a = row0 + wm + mt * 16 + gid;
#pragma unroll
        for (int nt = 0; nt < 4; nt++) {
            int col = e0 + wn + nt * 8 + 2 * tig;
            float2 v0 = make_float2(to_tf32(acc[mt][nt][0]), to_tf32(acc[mt][nt][1]));
            float2 v1 = make_float2(to_tf32(acc[mt][nt][2]), to_tf32(acc[mt][nt][3]));
            *(float2*)(g_vc + (long)r0a * EMB + col) = v0;
            *(float2*)(g_vc + (long)(r0a + 8) * EMB + col) = v1;
        }
    }
}

// Kernel 4: out = g_af @ Vc + bo   (pure tf32 GEMM; invcnt pre-folded in g_af)
__global__ __launch_bounds__(256, 2) void masked_gemm_kernel(
    const float* __restrict__ bo, float* __restrict__ Y)
{
    const int tid = threadIdx.x;
    const int wid = tid >> 5, lane = tid & 31;
    const int gid = lane >> 2, tig = lane & 3;
    const int wm = (wid >> 2) * 64;
    const int wn = (wid & 3) * 32;

    const int e0 = blockIdx.x * BN;
    const int row0 = blockIdx.y * BM;
    const int n = row0 / SEQ;

    float acc[4][4][4];
#pragma unroll
    for (int a = 0; a < 4; a++)
#pragma unroll
        for (int b = 0; b < 4; b++)
#pragma unroll
            for (int c = 0; c < 4; c++) acc[a][b][c] = 0.f;

    gemm_core<false>(g_af + (long)row0 * SEQ, SEQ,
                     g_vc + (long)n * SEQ * EMB + e0, acc, SEQ / BK);

#pragma unroll
    for (int mt = 0; mt < 4; mt++) {
        int r0a = row0 + wm + mt * 16 + gid;
#pragma unroll
        for (int nt = 0; nt < 4; nt++) {
            int col = e0 + wn + nt * 8 + 2 * tig;
            float b0v = bo[col], b1v = bo[col + 1];
            float2 v0 = make_float2(acc[mt][nt][0] + b0v, acc[mt][nt][1] + b1v);
            float2 v1 = make_float2(acc[mt][nt][2] + b0v, acc[mt][nt][3] + b1v);
            *(float2*)(Y + (long)r0a * EMB + col) = v0;
            *(float2*)(Y + (long)(r0a + 8) * EMB + col) = v1;
        }
    }
}

// ---------------------------------------------------------------------------
extern "C" void kernel_launch(void* const* d_in, const int* in_sizes, int n_in,
                              void* d_out, int out_size)
{
    const float* value = (const float*)d_in[0];
    // key/query/Wk/Wq unused: masked_fill(+1e20) before softmax forces all
    // unmasked scores to underflow; output is the masked average of projected V.
    const int*   mask  = (const int*)d_in[3];
    const float* Wv    = (const float*)d_in[4];
    const float* Wo    = (const float*)d_in[7];
    const float* bo    = (const float*)d_in[8];
    float* out = (float*)d_out;

    cudaFuncSetAttribute(vc_gemm_kernel,
                         cudaFuncAttributeMaxDynamicSharedMemorySize, GSMEM_BYTES);
    cudaFuncSetAttribute(masked_gemm_kernel,
                         cudaFuncAttributeMaxDynamicSharedMemorySize, GSMEM_BYTES);

    {
        dim3 grid(NHEADS, EMB / 64);
        wcomb_kernel<<<grid, 256>>>(Wv, Wo);
    }
    maskf_kernel<<<NB * SEQ, 256>>>(mask);
    {
        dim3 grid(EMB / BN, NB * SEQ / BM);
        vc_gemm_kernel<<<grid, 256, GSMEM_BYTES>>>(value);
    }
    {
        dim3 grid(EMB / BN, NB * SEQ / BM);
        masked_gemm_kernel<<<grid, 256, GSMEM_BYTES>>>(bo, out);
    }
}

// round 8
// speedup vs baseline: 26.8781x; 1.5724x over previous
#include <cuda_runtime.h>
#include <cuda_fp16.h>
#include <cstdint>

#define NB 2
#define SEQ 2048
#define EMB 1024
#define NHEADS 16

// Scratch (__device__ globals per allocation rules)
__device__ __half g_wh[EMB * EMB];          // folded Wv/Wo fp16: [k'][n]
__device__ __half g_vh[NB * SEQ * EMB];     // value as fp16
__device__ __half g_vch[NB * SEQ * EMB];    // Vc = value @ Wcomb, fp16
__device__ __half g_afh[NB * SEQ * SEQ];    // binary mask fp16: 1.0 where mask==0
__device__ float  g_invcnt[NB * SEQ];       // 1 / (# zeros in row), fp32

// ---------------------------------------------------------------------------
__device__ __forceinline__ void mma_f16(float c[4],
                                        uint32_t a0, uint32_t a1, uint32_t a2, uint32_t a3,
                                        uint32_t b0, uint32_t b1) {
    asm volatile(
        "mma.sync.aligned.m16n8k16.row.col.f32.f16.f16.f32 "
        "{%0,%1,%2,%3}, {%4,%5,%6,%7}, {%8,%9}, {%0,%1,%2,%3};"
        : "+f"(c[0]), "+f"(c[1]), "+f"(c[2]), "+f"(c[3])
        : "r"(a0), "r"(a1), "r"(a2), "r"(a3), "r"(b0), "r"(b1));
}

__device__ __forceinline__ void ldsm_x4(uint32_t& r0, uint32_t& r1,
                                        uint32_t& r2, uint32_t& r3, uint32_t addr) {
    asm volatile("ldmatrix.sync.aligned.m8n8.x4.shared.b16 {%0,%1,%2,%3}, [%4];"
                 : "=r"(r0), "=r"(r1), "=r"(r2), "=r"(r3) : "r"(addr));
}
__device__ __forceinline__ void ldsm_x4_t(uint32_t& r0, uint32_t& r1,
                                          uint32_t& r2, uint32_t& r3, uint32_t addr) {
    asm volatile("ldmatrix.sync.aligned.m8n8.x4.trans.shared.b16 {%0,%1,%2,%3}, [%4];"
                 : "=r"(r0), "=r"(r1), "=r"(r2), "=r"(r3) : "r"(addr));
}

__device__ __forceinline__ void cp16(uint32_t s, const void* g) {
    asm volatile("cp.async.cg.shared.global [%0], [%1], 16;" :: "r"(s), "l"(g));
}
__device__ __forceinline__ void cp_commit() { asm volatile("cp.async.commit_group;"); }
__device__ __forceinline__ void cp_wait0()  { asm volatile("cp.async.wait_group 0;"); }
__device__ __forceinline__ void cp_wait1()  { asm volatile("cp.async.wait_group 1;"); }
__device__ __forceinline__ void cp_wait2()  { asm volatile("cp.async.wait_group 2;"); }

// ---------------------------------------------------------------------------
// Kernel 1: Wcomb[h*64+d'][n] = sum_d Wv[d][d'] * Wo[n][h*64+d]  -> fp16
// ---------------------------------------------------------------------------
__global__ __launch_bounds__(256) void wcomb_kernel(
    const float* __restrict__ Wv, const float* __restrict__ Wo)
{
    __shared__ float sWv[64][68];
    __shared__ float sWoT[64][68];

    const int h = blockIdx.x;
    const int n0 = blockIdx.y * 64;
    const int tid = threadIdx.x;

    for (int i = tid; i < 4096; i += 256) {
        int d = i >> 6, r = i & 63;
        sWv[d][r] = Wv[i];
    }
    for (int i = tid; i < 4096; i += 256) {
        int c = i >> 6, d = i & 63;
        sWoT[d][c] = Wo[(long)(n0 + c) * EMB + h * 64 + d];
    }
    __syncthreads();

    const int tr = (tid >> 4) * 4, tc = (tid & 15) * 4;
    float acc[4][4];
#pragma unroll
    for (int i = 0; i < 4; i++)
#pragma unroll
        for (int j = 0; j < 4; j++) acc[i][j] = 0.f;

#pragma unroll
    for (int d = 0; d < 64; d++) {
        float4 av = *(const float4*)&sWv[d][tr];
        float4 bv = *(const float4*)&sWoT[d][tc];
        float a[4] = {av.x, av.y, av.z, av.w};
        float b[4] = {bv.x, bv.y, bv.z, bv.w};
#pragma unroll
        for (int i = 0; i < 4; i++)
#pragma unroll
            for (int j = 0; j < 4; j++) acc[i][j] += a[i] * b[j];
    }

#pragma unroll
    for (int i = 0; i < 4; i++) {
        __half2 h0 = __floats2half2_rn(acc[i][0], acc[i][1]);
        __half2 h1 = __floats2half2_rn(acc[i][2], acc[i][3]);
        uint2 w = make_uint2(*(uint32_t*)&h0, *(uint32_t*)&h1);
        *(uint2*)(g_wh + (long)(h * 64 + tr + i) * EMB + n0 + tc) = w;
    }
}

// ---------------------------------------------------------------------------
// Kernel 2: value fp32 -> fp16
// ---------------------------------------------------------------------------
__global__ __launch_bounds__(256) void cvtv_kernel(const float* __restrict__ V)
{
    long i = (long)blockIdx.x * 256 + threadIdx.x;    // float4 index
    float4 v = ((const float4*)V)[i];
    __half2 h0 = __floats2half2_rn(v.x, v.y);
    __half2 h1 = __floats2half2_rn(v.z, v.w);
    ((uint2*)g_vh)[i] = make_uint2(*(uint32_t*)&h0, *(uint32_t*)&h1);
}

// ---------------------------------------------------------------------------
// Kernel 3: mask row -> binary fp16 (1.0 where mask==0) + fp32 1/count
// ---------------------------------------------------------------------------
__global__ __launch_bounds__(256) void maskf_kernel(const int* __restrict__ mask)
{
    const int tid = threadIdx.x;
    const long base = (long)blockIdx.x * SEQ;
    const int4* mp = (const int4*)(mask + base);

    int4 a = mp[tid];
    int4 b = mp[tid + 256];
    int c = (a.x == 0) + (a.y == 0) + (a.z == 0) + (a.w == 0)
          + (b.x == 0) + (b.y == 0) + (b.z == 0) + (b.w == 0);

#pragma unroll
    for (int off = 16; off > 0; off >>= 1)
        c += __shfl_down_sync(0xffffffffu, c, off);

    __shared__ int ws[8];
    if ((tid & 31) == 0) ws[tid >> 5] = c;
    __syncthreads();
    if (tid == 0) {
        int t = 0;
#pragma unroll
        for (int i = 0; i < 8; i++) t += ws[i];
        g_invcnt[blockIdx.x] = 1.0f / (float)t;
    }

    const uint32_t ONE = 0x3C00u;  // fp16 1.0
    uint2 w0, w1;
    w0.x = ((a.x == 0) ? ONE : 0u) | (((a.y == 0) ? ONE : 0u) << 16);
    w0.y = ((a.z == 0) ? ONE : 0u) | (((a.w == 0) ? ONE : 0u) << 16);
    w1.x = ((b.x == 0) ? ONE : 0u) | (((b.y == 0) ? ONE : 0u) << 16);
    w1.y = ((b.z == 0) ? ONE : 0u) | (((b.w == 0) ? ONE : 0u) << 16);
    *(uint2*)(g_afh + base + tid * 4) = w0;
    *(uint2*)(g_afh + base + 1024 + tid * 4) = w1;
}

// ---------------------------------------------------------------------------
// fp16 GEMM: block 128x128, BK=32, 8 warps (2m x 4n), warp tile 64x32,
// m16n8k16 MMA, ldmatrix A (x4) + B (x4.trans), 4-stage cp.async, 2 CTAs/SM.
// A smem: rows padded to 40 halves (80B) -> bank-conflict-free ldsm, no swizzle.
// B smem: [k][128] halves, 16B-chunk XOR swizzle (c ^ (k&7)).
// ---------------------------------------------------------------------------
#define BM 128
#define BN 128
#define BK 32
#define NSTG 4
#define A_BYTES (BM * 40 * 2)          // 10240
#define B_BYTES (BK * BN * 2)          // 8192
#define GSMEM_BYTES (NSTG * (A_BYTES + B_BYTES))   // 73728

// tile loader: Ab/Bb are __half*, astride in elements; Bb pre-offset by e0.
__device__ __forceinline__ void gemm_load_h(uint32_t sA, uint32_t sB,
                                            const __half* Ab, long astride,
                                            const __half* Bb, int tid, int k0, int st)
{
#pragma unroll
    for (int u = 0; u < 2; u++) {
        int ch = tid + u * 256;            // 512 chunks: 128 rows x 4
        int r = ch >> 2, cc = ch & 3;
        cp16(sA + (uint32_t)(st * A_BYTES) + (uint32_t)(r * 40 + cc * 8) * 2,
             Ab + (long)r * astride + k0 + cc * 8);
    }
#pragma unroll
    for (int u = 0; u < 2; u++) {
        int ch = tid + u * 256;            // 512 chunks: 32 rows x 16
        int r = ch >> 4, cc = ch & 15;
        cp16(sB + (uint32_t)(st * B_BYTES) + (uint32_t)(r * 128 + ((cc ^ (r & 7)) * 8)) * 2,
             Bb + (long)(k0 + r) * EMB + cc * 8);
    }
    cp_commit();
}

__device__ __forceinline__ void gemm_core_h(const __half* Ab, long astride,
                                            const __half* Bb,
                                            float acc[4][4][4], int nIter)
{
    extern __shared__ char smh[];
    uint32_t sA = (uint32_t)__cvta_generic_to_shared(smh);
    uint32_t sB = sA + NSTG * A_BYTES;

    const int tid = threadIdx.x;
    const int wid = tid >> 5, lane = tid & 31;
    const int wm = (wid >> 2) * 64;
    const int wn = (wid & 3) * 32;

    const int lrow = lane & 15;
    const int lk8 = (lane & 16) >> 1;      // 0 or 8 (k element offset for A)
    const int bhi = (lane >> 4) & 1;       // B: +1 chunk for n+8 matrices

    // A per-mt byte offsets within a stage (add kb*2 at use)
    uint32_t aoff[4];
#pragma unroll
    for (int mt = 0; mt < 4; mt++)
        aoff[mt] = (uint32_t)((wm + mt * 16 + lrow) * 40 + lk8) * 2;

    gemm_load_h(sA, sB, Ab, astride, Bb, tid, 0, 0);
    gemm_load_h(sA, sB, Ab, astride, Bb, tid, BK, 1);
    gemm_load_h(sA, sB, Ab, astride, Bb, tid, 2 * BK, 2);

    for (int i = 0; i < nIter; i++) {
        if (i + 3 <= nIter) cp_wait2();
        else if (i + 2 == nIter) cp_wait1();
        else cp_wait0();
        __syncthreads();
        if (i + 3 < nIter)
            gemm_load_h(sA, sB, Ab, astride, Bb, tid, (i + 3) * BK, (i + 3) % NSTG);

        const int st = i % NSTG;
        const uint32_t aS = sA + (uint32_t)(st * A_BYTES);
        const uint32_t bS = sB + (uint32_t)(st * B_BYTES);

#pragma unroll
        for (int ks = 0; ks < 2; ks++) {
            const int kb = ks * 16;
            uint32_t a[4][4], br[2][4];
#pragma unroll
            for (int mt = 0; mt < 4; mt++)
                ldsm_x4(a[mt][0], a[mt][1], a[mt][2], a[mt][3],
                        aS + aoff[mt] + kb * 2);
#pragma unroll
            for (int nt2 = 0; nt2 < 2; nt2++) {
                int krow = kb + lrow;
                int nc = ((wn + nt2 * 16) >> 3) + bhi;
                int cs = nc ^ (krow & 7);
                ldsm_x4_t(br[nt2][0], br[nt2][1], br[nt2][2], br[nt2][3],
                          bS + (uint32_t)(krow * 128 + cs * 8) * 2);
            }
#pragma unroll
            for (int mt = 0; mt < 4; mt++)
#pragma unroll
                for (int nt = 0; nt < 4; nt++) {
                    int nt2 = nt >> 1, pr = (nt & 1) * 2;
                    mma_f16(acc[mt][nt], a[mt][0], a[mt][1], a[mt][2], a[mt][3],
                            br[nt2][pr], br[nt2][pr + 1]);
                }
        }
    }
}

// Kernel 4: Vc = g_vh @ g_wh  (fp16 in, fp32 acc, fp16 out)
__global__ __launch_bounds__(256, 2) void vc_gemm_kernel()
{
    const int tid = threadIdx.x;
    const int wid = tid >> 5, lane = tid & 31;
    const int gid = lane >> 2, tig = lane & 3;
    const int wm = (wid >> 2) * 64;
    const int wn = (wid & 3) * 32;

    const int e0 = blockIdx.x * BN;
    const int row0 = blockIdx.y * BM;

    float acc[4][4][4];
#pragma unroll
    for (int a = 0; a < 4; a++)
#pragma unroll
        for (int b = 0; b < 4; b++)
#pragma unroll
            for (int c = 0; c < 4; c++) acc[a][b][c] = 0.f;

    gemm_core_h(g_vh + (long)row0 * EMB, EMB, g_wh + e0, acc, EMB / BK);

#pragma unroll
    for (int mt = 0; mt < 4; mt++) {
        int r0a = row0 + wm + mt * 16 + gid;
#pragma unroll
        for (int nt = 0; nt < 4; nt++) {
            int col = e0 + wn + nt * 8 + 2 * tig;
            __half2 h0 = __floats2half2_rn(acc[mt][nt][0], acc[mt][nt][1]);
            __half2 h1 = __floats2half2_rn(acc[mt][nt][2], acc[mt][nt][3]);
            *(__half2*)(g_vch + (long)r0a * EMB + col) = h0;
            *(__half2*)(g_vch + (long)(r0a + 8) * EMB + col) = h1;
        }
    }
}

// Kernel 5: out = diag(invcnt) * (g_afh @ g_vch) + bo
__global__ __launch_bounds__(256, 2) void masked_gemm_kernel(
    const float* __restrict__ bo, float* __restrict__ Y)
{
    const int tid = threadIdx.x;
    const int wid = tid >> 5, lane = tid & 31;
    const int gid = lane >> 2, tig = lane & 3;
    const int wm = (wid >> 2) * 64;
    const int wn = (wid & 3) * 32;

    const int e0 = blockIdx.x * BN;
    const int row0 = blockIdx.y * BM;
    const int n = row0 / SEQ;

    float acc[4][4][4];
#pragma unroll
    for (int a = 0; a < 4; a++)
#pragma unroll
        for (int b = 0; b < 4; b++)
#pragma unroll
            for (int c = 0; c < 4; c++) acc[a][b][c] = 0.f;

    gemm_core_h(g_afh + (long)row0 * SEQ, SEQ,
                g_vch + (long)n * SEQ * EMB + e0, acc, SEQ / BK);

#pragma unroll
    for (int mt = 0; mt < 4; mt++) {
        int r0a = row0 + wm + mt * 16 + gid;
        float s0 = g_invcnt[r0a];
        float s1 = g_invcnt[r0a + 8];
#pragma unroll
        for (int nt = 0; nt < 4; nt++) {
            int col = e0 + wn + nt * 8 + 2 * tig;
            float b0v = bo[col], b1v = bo[col + 1];
            float2 v0 = make_float2(acc[mt][nt][0] * s0 + b0v, acc[mt][nt][1] * s0 + b1v);
            float2 v1 = make_float2(acc[mt][nt][2] * s1 + b0v, acc[mt][nt][3] * s1 + b1v);
            *(float2*)(Y + (long)r0a * EMB + col) = v0;
            *(float2*)(Y + (long)(r0a + 8) * EMB + col) = v1;
        }
    }
}

// ---------------------------------------------------------------------------
extern "C" void kernel_launch(void* const* d_in, const int* in_sizes, int n_in,
                              void* d_out, int out_size)
{
    const float* value = (const float*)d_in[0];
    // key/query/Wk/Wq unused: masked_fill(+1e20) before softmax forces all
    // unmasked scores to underflow; output is the masked average of projected V.
    const int*   mask  = (const int*)d_in[3];
    const float* Wv    = (const float*)d_in[4];
    const float* Wo    = (const float*)d_in[7];
    const float* bo    = (const float*)d_in[8];
    float* out = (float*)d_out;

    cudaFuncSetAttribute(vc_gemm_kernel,
                         cudaFuncAttributeMaxDynamicSharedMemorySize, GSMEM_BYTES);
    cudaFuncSetAttribute(masked_gemm_kernel,
                         cudaFuncAttributeMaxDynamicSharedMemorySize, GSMEM_BYTES);

    {
        dim3 grid(NHEADS, EMB / 64);
        wcomb_kernel<<<grid, 256>>>(Wv, Wo);
    }
    cvtv_kernel<<<NB * SEQ * EMB / 4 / 256, 256>>>(value);
    maskf_kernel<<<NB * SEQ, 256>>>(mask);
    {
        dim3 grid(EMB / BN, NB * SEQ / BM);
        vc_gemm_kernel<<<grid, 256, GSMEM_BYTES>>>();
    }
    {
        dim3 grid(EMB / BN, NB * SEQ / BM);
        masked_gemm_kernel<<<grid, 256, GSMEM_BYTES>>>(bo, out);
    }
}